// round 11
// baseline (speedup 1.0000x reference)
#include <cuda_runtime.h>
#include <cuda_fp16.h>

#define BB    4
#define NQ    2048
#define DIMK  1024
#define HEADS 16
#define DH    64
#define INNER 1024
#define NCOLS 3072
#define SPLIT 4

#define A_ELEMS (BB*NQ*INNER)
#define M_ELEMS (BB*HEADS*DH*DH)

__device__ __half g_qh[BB*HEADS*NQ*DH];
__device__ __half g_kh[BB*HEADS*NQ*DH];
__device__ __half g_vh[BB*HEADS*NQ*DH];
__device__ __half g_xh[BB*NQ*DIMK];
__device__ __half g_wh[DIMK*NCOLS];
__device__ float  g_mpart[BB*HEADS*SPLIT*DH*DH];
__device__ float  g_zpart[BB*HEADS*SPLIT*DH];
__device__ unsigned g_cnt[BB*HEADS];

__device__ __forceinline__ void mmah(float* c, const unsigned* a, const unsigned* b) {
    asm volatile(
        "mma.sync.aligned.m16n8k16.row.col.f32.f16.f16.f32 "
        "{%0,%1,%2,%3}, {%4,%5,%6,%7}, {%8,%9}, {%0,%1,%2,%3};\n"
        : "+f"(c[0]), "+f"(c[1]), "+f"(c[2]), "+f"(c[3])
        : "r"(a[0]), "r"(a[1]), "r"(a[2]), "r"(a[3]), "r"(b[0]), "r"(b[1]));
}
__device__ __forceinline__ void ldsm_x4(unsigned* r, unsigned addr) {
    asm volatile("ldmatrix.sync.aligned.m8n8.x4.shared.b16 {%0,%1,%2,%3}, [%4];"
        : "=r"(r[0]), "=r"(r[1]), "=r"(r[2]), "=r"(r[3]) : "r"(addr));
}
__device__ __forceinline__ void ldsm_x4_t(unsigned* r, unsigned addr) {
    asm volatile("ldmatrix.sync.aligned.m8n8.x4.trans.shared.b16 {%0,%1,%2,%3}, [%4];"
        : "=r"(r[0]), "=r"(r[1]), "=r"(r[2]), "=r"(r[3]) : "r"(addr));
}
__device__ __forceinline__ void ldsm_x2_t(unsigned* r, unsigned addr) {
    asm volatile("ldmatrix.sync.aligned.m8n8.x2.trans.shared.b16 {%0,%1}, [%2];"
        : "=r"(r[0]), "=r"(r[1]) : "r"(addr));
}
__device__ __forceinline__ unsigned packh2(float a, float b) {
    __half2 h = __floats2half2_rn(a, b);
    return *(unsigned*)&h;
}
__device__ __forceinline__ unsigned ex2h2(float a, float b) {
    unsigned p = packh2(a, b);
    unsigned r; asm("ex2.approx.f16x2 %0, %1;" : "=r"(r) : "r"(p));
    return r;
}
__device__ __forceinline__ float sigma_f(float f) {
    return (f > 0.f) ? (f + 1.f) : __expf(f);
}
__device__ __forceinline__ unsigned sptr(const void* p) {
    return (unsigned)__cvta_generic_to_shared(p);
}
#define CP16(dst, src) asm volatile("cp.async.ca.shared.global [%0], [%1], 16;" :: "r"(dst), "l"(src))
#define CP_COMMIT()    asm volatile("cp.async.commit_group;")
#define CP_WAIT0()     asm volatile("cp.async.wait_group 0;")
#define CP_WAIT1()     asm volatile("cp.async.wait_group 1;")

// ---------------------------------------------------------------------------
// Kernel 0: x, W -> half
// ---------------------------------------------------------------------------
__global__ __launch_bounds__(256)
void preconv(const float* __restrict__ x, const float* __restrict__ W) {
    const int nx = BB*NQ*DIMK/4;
    const int nw = DIMK*NCOLS/4;
    int i = blockIdx.x*256 + threadIdx.x;
    if (i < nx) {
        float4 v = ((const float4*)x)[i];
        ((__half2*)g_xh)[2*i]   = __floats2half2_rn(v.x, v.y);
        ((__half2*)g_xh)[2*i+1] = __floats2half2_rn(v.z, v.w);
    } else if (i < nx + nw) {
        int j = i - nx;
        float4 v = ((const float4*)W)[j];
        ((__half2*)g_wh)[2*j]   = __floats2half2_rn(v.x, v.y);
        ((__half2*)g_wh)[2*j+1] = __floats2half2_rn(v.z, v.w);
    }
}

// ---------------------------------------------------------------------------
// Kernel 1: QKV GEMM fp16 mma, BK=32, 3-stage cp.async pipeline (unchanged)
// ---------------------------------------------------------------------------
#define QA_STG (128*40)
#define QB_STG (32*136)
#define QKV_SMEM_BYTES ((3*QA_STG + 3*QB_STG)*2)

__global__ __launch_bounds__(256, 2)
void qkv_gemm(void) {
    extern __shared__ __align__(16) __half qsm[];
    __half* As = qsm;
    __half* Bs = qsm + 3*QA_STG;

    const int tid  = threadIdx.x;
    const int bm   = blockIdx.y * 128, bn = blockIdx.x * 128;
    const int wid  = tid >> 5, lane = tid & 31;
    const int wm   = (wid & 1) * 64, wn = (wid >> 1) * 32;
    const int lr   = lane >> 2, lc = lane & 3;

    const int ar = tid >> 2, ach = tid & 3;
    const int br = tid >> 4, bch = tid & 15;
    const __half* asrc0 = g_xh + (size_t)(bm + ar) * DIMK + ach*8;
    const __half* asrc1 = asrc0 + (size_t)64 * DIMK;
    const __half* bsrc0 = g_wh + (size_t)br * NCOLS + bn + bch*8;
    const __half* bsrc1 = bsrc0 + (size_t)16 * NCOLS;
    const unsigned a_off = sptr(&As[ar*40 + ach*8]);
    const unsigned b_off = sptr(&Bs[br*136 + bch*8]);

    #pragma unroll
    for (int s = 0; s < 2; ++s) {
        int ko = s * 32;
        CP16(a_off + s*QA_STG*2, asrc0 + ko);
        CP16(a_off + s*QA_STG*2 + 64*40*2, asrc1 + ko);
        CP16(b_off + s*QB_STG*2, bsrc0 + (size_t)ko * NCOLS);
        CP16(b_off + s*QB_STG*2 + 16*136*2, bsrc1 + (size_t)ko * NCOLS);
        CP_COMMIT();
    }

    float cacc[4][4][4];
    #pragma unroll
    for (int i = 0; i < 4; i++)
        #pragma unroll
        for (int j = 0; j < 4; j++) { cacc[i][j][0]=0.f; cacc[i][j][1]=0.f; cacc[i][j][2]=0.f; cacc[i][j][3]=0.f; }

    const int l15 = lane & 15;
    const int lhi8 = (lane & 16) >> 1;
    int cur = 0;
    for (int kt = 0; kt < DIMK/32; ++kt) {
        CP_WAIT1();
        __syncthreads();
        if (kt + 2 < DIMK/32) {
            int ko = (kt + 2) * 32;
            int nxs = (cur + 2) % 3;
            CP16(a_off + nxs*QA_STG*2, asrc0 + ko);
            CP16(a_off + nxs*QA_STG*2 + 64*40*2, asrc1 + ko);
            CP16(b_off + nxs*QB_STG*2, bsrc0 + (size_t)ko * NCOLS);
            CP16(b_off + nxs*QB_STG*2 + 16*136*2, bsrc1 + (size_t)ko * NCOLS);
            CP_COMMIT();
        }

        const __half* Ah = As + cur*QA_STG;
        const __half* Bh = Bs + cur*QB_STG;
        #pragma unroll
        for (int ks = 0; ks < 2; ++ks) {
            unsigned af[4][4];
            #pragma unroll
            for (int mt = 0; mt < 4; ++mt)
                ldsm_x4(af[mt], sptr(&Ah[(wm + mt*16 + l15)*40 + ks*16 + lhi8]));
            #pragma unroll
            for (int ntp = 0; ntp < 2; ++ntp) {
                unsigned bf[4];
                ldsm_x4_t(bf, sptr(&Bh[(ks*16 + l15)*136 + wn + ntp*16 + lhi8]));
                #pragma unroll
                for (int mt = 0; mt < 4; ++mt) {
                    mmah(cacc[mt][2*ntp],   af[mt], bf);
                    mmah(cacc[mt][2*ntp+1], af[mt], bf + 2);
                }
            }
        }
        cur = (cur + 1) % 3;
    }

    const int part = (bn + wn) >> 10;
    __half* dst = (part == 0) ? g_qh : (part == 1) ? g_kh : g_vh;
    #pragma unroll
    for (int mt = 0; mt < 4; ++mt) {
        int r0 = bm + wm + mt*16 + lr;
        #pragma unroll
        for (int nt = 0; nt < 4; ++nt) {
            int cg = bn + wn + nt*8 + 2*lc;
            int hh = (cg >> 6) & (HEADS - 1);
            int dd = cg & 63;
            int bi = r0 >> 11, nn = r0 & 2047;
            size_t off = (((size_t)(bi*HEADS + hh) * NQ + nn) * DH) + dd;
            int r1 = r0 + 8;
            int bi1 = r1 >> 11, nn1 = r1 & 2047;
            size_t off2 = (((size_t)(bi1*HEADS + hh) * NQ + nn1) * DH) + dd;
            *(unsigned*)&dst[off]  = packh2(cacc[mt][nt][0], cacc[mt][nt][1]);
            *(unsigned*)&dst[off2] = packh2(cacc[mt][nt][2], cacc[mt][nt][3]);
        }
    }
}

// ---------------------------------------------------------------------------
// Kernel 2: fp16 flash attention, static-shift softmax, SOFTWARE-PIPELINED:
// iteration i runs PV(tile i) interleaved with S(tile i+1). 3-stage K/V ring.
// smem: KH[3][64*72] | VH[3][64*88] | Zs[64]
// ---------------------------------------------------------------------------
#define KTK (64*72)
#define KTV (64*88)
#define NTILES (NQ/64)
#define ATT_SMEM_BYTES ((3*KTK + 3*KTV)*2 + 64*4)
#define SCL2 0.1803368801111204f

__global__ __launch_bounds__(256, 2)
void attn_k(const float* __restrict__ M_in, const float* __restrict__ Z_in,
            const float* __restrict__ beta_gate, float* __restrict__ outA) {
    extern __shared__ __align__(16) __half smh[];
    __half* KH = smh;
    __half* VH = smh + 3*KTK;
    float*  Zs = (float*)(smh + 3*KTK + 3*KTV);

    const int tid = threadIdx.x, wid = tid >> 5, lane = tid & 31;
    const int lr = lane >> 2, lc = lane & 3;
    const int l15 = lane & 15;
    const int l7  = lane & 7;
    const int lhi8 = (lane & 16) >> 1;
    const int b = blockIdx.z, h = blockIdx.y, bh = b*HEADS + h;
    const int qb = blockIdx.x * 128;
    const int rowA = wid*16 + lr;

    const __half* qg = g_qh + ((size_t)bh*NQ + qb)*DH;
    const __half* kg = g_kh + (size_t)bh*NQ*DH;
    const __half* vg = g_vh + (size_t)bh*NQ*DH;

    const int cr = tid >> 3, cch = tid & 7;
    const unsigned k_off = sptr(&KH[cr*72 + cch*8]);
    const unsigned v_off = sptr(&VH[cr*88 + cch*8]);
    const __half* ksrc = kg + (size_t)cr*DH + cch*8;
    const __half* vsrc = vg + (size_t)cr*DH + cch*8;
    #define KROW32 (32*72*2)
    #define VROW32 (32*88*2)

    // ones-column region (cols 64..71) of all 3 V buffers
    for (int i = tid; i < 192; i += 256) {
        int buf = i >> 6, r = i & 63;
        __half* vrow = VH + buf*KTV + r*88 + 64;
        vrow[0] = __float2half(1.f);
        #pragma unroll
        for (int c = 1; c < 8; ++c) vrow[c] = __float2half(0.f);
    }

    unsigned qa[4][4];
    #pragma unroll
    for (int ks = 0; ks < 4; ++ks) {
        qa[ks][0] = *(const unsigned*)&qg[(size_t)rowA*DH + ks*16 + 2*lc];
        qa[ks][1] = *(const unsigned*)&qg[(size_t)(rowA+8)*DH + ks*16 + 2*lc];
        qa[ks][2] = *(const unsigned*)&qg[(size_t)rowA*DH + ks*16 + 2*lc + 8];
        qa[ks][3] = *(const unsigned*)&qg[(size_t)(rowA+8)*DH + ks*16 + 2*lc + 8];
    }

    // stage tiles 0 and 1
    #pragma unroll
    for (int s = 0; s < 2; ++s) {
        const __half* kn = ksrc + (size_t)(s*64)*DH;
        const __half* vn = vsrc + (size_t)(s*64)*DH;
        CP16(k_off + s*KTK*2, kn); CP16(k_off + s*KTK*2 + KROW32, kn + 32*DH);
        CP16(v_off + s*KTV*2, vn); CP16(v_off + s*KTV*2 + VROW32, vn + 32*DH);
        CP_COMMIT();
    }

    float oacc[8][4];
    #pragma unroll
    for (int i = 0; i < 8; i++) { oacc[i][0]=0.f; oacc[i][1]=0.f; oacc[i][2]=0.f; oacc[i][3]=0.f; }
    float osum[4] = {0.f, 0.f, 0.f, 0.f};
    unsigned acur[4][4];

    // prologue: S(0) and exp -> acur
    {
        CP_WAIT1();
        __syncthreads();
        float sacc[8][4];
        #pragma unroll
        for (int i = 0; i < 8; i++) { sacc[i][0]=0.f; sacc[i][1]=0.f; sacc[i][2]=0.f; sacc[i][3]=0.f; }
        #pragma unroll
        for (int ks = 0; ks < 4; ++ks) {
            #pragma unroll
            for (int ntp = 0; ntp < 4; ++ntp) {
                unsigned kb[4];
                ldsm_x4(kb, sptr(&KH[(ntp*16 + l7 + lhi8)*72 + ks*16 + (lane & 8)]));
                mmah(sacc[2*ntp],   qa[ks], kb);
                mmah(sacc[2*ntp+1], qa[ks], kb + 2);
            }
        }
        #pragma unroll
        for (int ks = 0; ks < 4; ++ks) {
            acur[ks][0] = ex2h2(sacc[2*ks][0]*SCL2,   sacc[2*ks][1]*SCL2);
            acur[ks][1] = ex2h2(sacc[2*ks][2]*SCL2,   sacc[2*ks][3]*SCL2);
            acur[ks][2] = ex2h2(sacc[2*ks+1][0]*SCL2, sacc[2*ks+1][1]*SCL2);
            acur[ks][3] = ex2h2(sacc[2*ks+1][2]*SCL2, sacc[2*ks+1][3]*SCL2);
        }
    }

    for (int i = 0; i < NTILES; ++i) {
        CP_WAIT0();
        __syncthreads();
        if (i + 2 < NTILES) {
            int bs = (i + 2) % 3;
            const __half* kn = ksrc + (size_t)((i+2)*64)*DH;
            const __half* vn = vsrc + (size_t)((i+2)*64)*DH;
            CP16(k_off + bs*KTK*2, kn); CP16(k_off + bs*KTK*2 + KROW32, kn + 32*DH);
            CP16(v_off + bs*KTV*2, vn); CP16(v_off + bs*KTV*2 + VROW32, vn + 32*DH);
            CP_COMMIT();
        }
        const __half* Vc = VH + (i % 3)*KTV;
        const __half* Kc = KH + ((i + 1) % 3)*KTK;
        const bool hasS = (i + 1 < NTILES);

        float sacc[8][4];
        #pragma unroll
        for (int j = 0; j < 8; j++) { sacc[j][0]=0.f; sacc[j][1]=0.f; sacc[j][2]=0.f; sacc[j][3]=0.f; }

        // interleaved: S(i+1) chunk + PV(i) chunk per ks
        #pragma unroll
        for (int ks = 0; ks < 4; ++ks) {
            if (hasS) {
                #pragma unroll
                for (int ntp = 0; ntp < 4; ++ntp) {
                    unsigned kb[4];
                    ldsm_x4(kb, sptr(&Kc[(ntp*16 + l7 + lhi8)*72 + ks*16 + (lane & 8)]));
                    mmah(sacc[2*ntp],   qa[ks], kb);
                    mmah(sacc[2*ntp+1], qa[ks], kb + 2);
                }
            }
            #pragma unroll
            for (int ntp = 0; ntp < 4; ++ntp) {
                unsigned vb[4];
                ldsm_x4_t(vb, sptr(&Vc[(ks*16 + l15)*88 + ntp*16 + lhi8]));
                mmah(oacc[2*ntp],   acur[ks], vb);
                mmah(oacc[2*ntp+1], acur[ks], vb + 2);
            }
            unsigned vs[2];
            ldsm_x2_t(vs, sptr(&Vc[(ks*16 + l15)*88 + 64]));
            mmah(osum, acur[ks], vs);
        }

        if (hasS) {
            #pragma unroll
            for (int ks = 0; ks < 4; ++ks) {
                acur[ks][0] = ex2h2(sacc[2*ks][0]*SCL2,   sacc[2*ks][1]*SCL2);
                acur[ks][1] = ex2h2(sacc[2*ks][2]*SCL2,   sacc[2*ks][3]*SCL2);
                acur[ks][2] = ex2h2(sacc[2*ks+1][0]*SCL2, sacc[2*ks+1][1]*SCL2);
                acur[ks][3] = ex2h2(sacc[2*ks+1][2]*SCL2, sacc[2*ks+1][3]*SCL2);
            }
        }
    }

    float l1 = __shfl_sync(0xffffffffu, osum[0], lane & 28);
    float l2 = __shfl_sync(0xffffffffu, osum[2], lane & 28);

    // epilogue: A_mem = sigma(Q) @ M via fp16 mma
    __syncthreads();
    const float* Mg = M_in + (size_t)bh*DH*DH;
    __half* Mh = KH;
    for (int i = tid; i < DH*DH; i += 256) {
        int d = i >> 6, v = i & 63;
        Mh[d*72 + v] = __float2half_rn(Mg[i]);
    }
    if (tid < DH) Zs[tid] = Z_in[bh*DH + tid];
    __syncthreads();

    float macc[8][4];
    #pragma unroll
    for (int i = 0; i < 8; i++) { macc[i][0]=0.f; macc[i][1]=0.f; macc[i][2]=0.f; macc[i][3]=0.f; }
    float den1 = 0.f, den2 = 0.f;

    #pragma unroll
    for (int ks = 0; ks < 4; ++ks) {
        unsigned a[4];
        int c0 = ks*16 + 2*lc;
        float2 f0 = __half22float2(*(__half2*)&qa[ks][0]);
        float2 f1 = __half22float2(*(__half2*)&qa[ks][1]);
        float2 f2 = __half22float2(*(__half2*)&qa[ks][2]);
        float2 f3 = __half22float2(*(__half2*)&qa[ks][3]);
        float s00 = sigma_f(f0.x), s01 = sigma_f(f0.y);
        float s10 = sigma_f(f1.x), s11 = sigma_f(f1.y);
        float s20 = sigma_f(f2.x), s21 = sigma_f(f2.y);
        float s30 = sigma_f(f3.x), s31 = sigma_f(f3.y);
        a[0] = packh2(s00, s01); a[1] = packh2(s10, s11);
        a[2] = packh2(s20, s21); a[3] = packh2(s30, s31);
        den1 += s00*Zs[c0] + s01*Zs[c0+1] + s20*Zs[c0+8] + s21*Zs[c0+9];
        den2 += s10*Zs[c0] + s11*Zs[c0+1] + s30*Zs[c0+8] + s31*Zs[c0+9];
        #pragma unroll
        for (int ntp = 0; ntp < 4; ++ntp) {
            unsigned mb[4];
            ldsm_x4_t(mb, sptr(&Mh[(ks*16 + l15)*72 + ntp*16 + lhi8]));
            mmah(macc[2*ntp],   a, mb);
            mmah(macc[2*ntp+1], a, mb + 2);
        }
    }
    den1 += __shfl_xor_sync(0xffffffffu, den1, 1);
    den1 += __shfl_xor_sync(0xffffffffu, den1, 2);
    den2 += __shfl_xor_sync(0xffffffffu, den2, 1);
    den2 += __shfl_xor_sync(0xffffffffu, den2, 2);

    float g = 1.f / (1.f + __expf(-beta_gate[h]));
    float iv1 = 1.f/l1, iv2 = 1.f/l2, id1 = 1.f/den1, id2 = 1.f/den2;

    int n1 = qb + rowA;
    float* o1 = outA + ((size_t)(b*NQ + n1))*INNER + h*DH;
    float* o2 = o1 + (size_t)8*INNER;
    #pragma unroll
    for (int nt = 0; nt < 8; ++nt) {
        int d = nt*8 + 2*lc;
        *(float2*)&o1[d] = make_float2(
            g*macc[nt][0]*id1 + (1.f-g)*oacc[nt][0]*iv1,
            g*macc[nt][1]*id1 + (1.f-g)*oacc[nt][1]*iv1);
        *(float2*)&o2[d] = make_float2(
            g*macc[nt][2]*id2 + (1.f-g)*oacc[nt][2]*iv2,
            g*macc[nt][3]*id2 + (1.f-g)*oacc[nt][3]*iv2);
    }
}

// ---------------------------------------------------------------------------
// Kernel 3: state partials via fp16 mma + fused last-CTA reduction (unchanged)
// ---------------------------------------------------------------------------
#define ST_SMEM_BYTES ((3*64*72)*2 + 128*4)

__global__ __launch_bounds__(256)
void state_part(const float* __restrict__ M_in, const float* __restrict__ Z_in,
                const float* __restrict__ beta_lin, float* __restrict__ out) {
    extern __shared__ __align__(16) __half sst[];
    __half* Sksh = sst;
    __half* Vsh  = sst + 64*72;
    __half* Mth  = sst + 2*64*72;
    float*  Zs   = (float*)(sst + 3*64*72);
    float*  invden = Zs + 64;
    __shared__ unsigned slast;

    const int tid = threadIdx.x, wid = tid >> 5, lane = tid & 31;
    const int lr = lane >> 2, lc = lane & 3;
    const int l15 = lane & 15, l7 = lane & 7;
    const int lhi8 = (lane & 16) >> 1;
    const int bh = blockIdx.x >> 2;
    const int chunk = blockIdx.x & 3;
    const int nrows = NQ / SPLIT;
    const int rt = wid & 3, ct = wid >> 2;

    const float* Mg = M_in + (size_t)bh*DH*DH;
    for (int i = tid; i < DH*DH; i += 256) {
        int d = i >> 6, v = i & 63;
        Mth[v*72 + d] = __float2half_rn(Mg[i]);
    }
    if (tid < DH) Zs[tid] = Z_in[bh*DH + tid];

    const __half* kg = g_kh + ((size_t)bh*NQ + (size_t)chunk*nrows)*DH;
    const __half* vg = g_vh + ((size_t)bh*NQ + (size_t)chunk*nrows)*DH;

    float macc[4][4];
    #pragma unroll
    for (int i = 0; i < 4; i++) { macc[i][0]=0.f; macc[i][1]=0.f; macc[i][2]=0.f; macc[i][3]=0.f; }
    float zpart = 0.f;
    const int dz = wid*8 + lr;

    for (int n0 = 0; n0 < nrows; n0 += 64) {
        __syncthreads();
        #pragma unroll
        for (int t = 0; t < 2; ++t) {
            int c = tid + 256*t;
            int r = c >> 3, s8 = (c & 7) << 3;
            const __half2* kp = (const __half2*)&kg[(size_t)(n0+r)*DH + s8];
            __half2 h2[4];
            #pragma unroll
            for (int u = 0; u < 4; ++u) {
                float2 f = __half22float2(kp[u]);
                h2[u] = __floats2half2_rn(sigma_f(f.x), sigma_f(f.y));
            }
            *(uint4*)&Sksh[r*72 + s8] = *(uint4*)h2;
            *(uint4*)&Vsh[r*72 + s8] = *(const uint4*)&vg[(size_t)(n0+r)*DH + s8];
        }
        __syncthreads();

        {
            int rn = wid*8 + lr;
            float acc = 0.f;
            const __half2* sp = (const __half2*)&Sksh[rn*72 + lc*16];
            #pragma unroll
            for (int j = 0; j < 8; ++j) {
                float2 f = __half22float2(sp[j]);
                acc += f.x*Zs[lc*16 + 2*j] + f.y*Zs[lc*16 + 2*j + 1];
            }
            acc += __shfl_xor_sync(0xffffffffu, acc, 1);
            acc += __shfl_xor_sync(0xffffffffu, acc, 2);
            if (lc == 0) invden[rn] = 1.f / acc;
            #pragma unroll
            for (int j = 0; j < 16; ++j)
                zpart += __half2float(Sksh[(lc*16 + j)*72 + dz]);
        }
        __syncthreads();

        float pacc[4][4];
        #pragma unroll
        for (int i = 0; i < 4; i++) { pacc[i][0]=0.f; pacc[i][1]=0.f; pacc[i][2]=0.f; pacc[i][3]=0.f; }
        #pragma unroll
        for (int ks = 0; ks < 4; ++ks) {
            unsigned af[4];
            ldsm_x4(af, sptr(&Sksh[(rt*16 + l15)*72 + ks*16 + lhi8]));
            #pragma unroll
            for (int ntp = 0; ntp < 2; ++ntp) {
                unsigned bf[4];
                ldsm_x4(bf, sptr(&Mth[(ct*32 + ntp*16 + l7 + lhi8)*72 + ks*16 + (lane & 8)]));
                mmah(pacc[2*ntp],   af, bf);
                mmah(pacc[2*ntp+1], af, bf + 2);
            }
        }

        {
            int r0 = rt*16 + lr, r1 = r0 + 8;
            float iv0 = invden[r0], iv1 = invden[r1];
            #pragma unroll
            for (int nt = 0; nt < 4; ++nt) {
                int c0 = ct*32 + nt*8 + 2*lc;
                float2 fv0 = __half22float2(*(__half2*)&Vsh[r0*72 + c0]);
                *(__half2*)&Vsh[r0*72 + c0] =
                    __floats2half2_rn(fv0.x - pacc[nt][0]*iv0, fv0.y - pacc[nt][1]*iv0);
                float2 fv1 = __half22float2(*(__half2*)&Vsh[r1*72 + c0]);
                *(__half2*)&Vsh[r1*72 + c0] =
                    __floats2half2_rn(fv1.x - pacc[nt][2]*iv1, fv1.y - pacc[nt][3]*iv1);
            }
        }
        __syncthreads();

        #pragma unroll
        for (int ks = 0; ks < 4; ++ks) {
            unsigned a[4];
            ldsm_x4_t(a, sptr(&Sksh[(ks*16 + l7 + lhi8)*72 + rt*16 + (lane & 8)]));
            #pragma unroll
            for (int ntp = 0; ntp < 2; ++ntp) {
                unsigned bf[4];
                ldsm_x4_t(bf, sptr(&Vsh[(ks*16 + l15)*72 + ct*32 + ntp*16 + lhi8]));
                mmah(macc[2*ntp],   a, bf);
                mmah(macc[2*ntp+1], a, bf + 2);
            }
        }
    }

    float* mp = g_mpart + (size_t)blockIdx.x * DH*DH;
    int d0 = rt*16 + lr, d1 = d0 + 8;
    #pragma unroll
    for (int nt = 0; nt < 4; ++nt) {
        int c0 = ct*32 + nt*8 + 2*lc;
        *(float2*)&mp[d0*DH + c0] = make_float2(macc[nt][0], macc[nt][1]);
        *(float2*)&mp[d1*DH + c0] = make_float2(macc[nt][2], macc[nt][3]);
    }
    zpart += __shfl_xor_sync(0xffffffffu, zpart, 1);
    zpart += __shfl_xor_sync(0xffffffffu, zpart, 2);
    if (lc == 0) g_zpart[blockIdx.x*DH + dz] = zpart;

    __threadfence();
    if (tid == 0) slast = atomicInc(&g_cnt[bh], SPLIT - 1);
    __syncthreads();
    if (slast == SPLIT - 1) {
        float beta = 1.f / (1.f + __expf(-beta_lin[0]));
        beta = fminf(fmaxf(beta, 0.9f), 0.999f);
        float* mo = out + A_ELEMS + (size_t)bh*DH*DH;
        for (int e = tid; e < DH*DH; e += 256) {
            float s = beta*Mg[e];
            #pragma unroll
            for (int c = 0; c < SPLIT; ++c)
                s += g_mpart[(size_t)(bh*SPLIT + c)*DH*DH + e];
            mo[e] = s;
        }
        if (tid < DH) {
            float z = 0.f;
            #pragma unroll
            for (int c = 0; c < SPLIT; ++c)
                z += g_zpart[(bh*SPLIT + c)*DH + tid];
            out[A_ELEMS + M_ELEMS + bh*DH + tid] = beta*Z_in[bh*DH + tid] + z;
        }
    }
}

// ---------------------------------------------------------------------------
extern "C" void kernel_launch(void* const* d_in, const int* in_sizes, int n_in,
                              void* d_out, int out_size) {
    const float* x         = (const float*)d_in[0];
    const float* M         = (const float*)d_in[1];
    const float* Z         = (const float*)d_in[2];
    const float* W         = (const float*)d_in[3];
    const float* beta_lin  = (const float*)d_in[4];
    const float* beta_gate = (const float*)d_in[5];
    float* out = (float*)d_out;

    cudaFuncSetAttribute(qkv_gemm, cudaFuncAttributeMaxDynamicSharedMemorySize, QKV_SMEM_BYTES);
    cudaFuncSetAttribute(attn_k, cudaFuncAttributeMaxDynamicSharedMemorySize, ATT_SMEM_BYTES);
    cudaFuncSetAttribute(state_part, cudaFuncAttributeMaxDynamicSharedMemorySize, ST_SMEM_BYTES);

    const int npc = (BB*NQ*DIMK + DIMK*NCOLS)/4;
    preconv<<<(npc + 255)/256, 256>>>(x, W);
    qkv_gemm<<<dim3(NCOLS/128, (BB*NQ)/128), 256, QKV_SMEM_BYTES>>>();
    attn_k<<<dim3(NQ/128, HEADS, BB), 256, ATT_SMEM_BYTES>>>(M, Z, beta_gate, out);
    state_part<<<BB*HEADS*SPLIT, 256, ST_SMEM_BYTES>>>(M, Z, beta_lin, out);
}

// round 12
// speedup vs baseline: 1.0553x; 1.0553x over previous
#include <cuda_runtime.h>
#include <cuda_fp16.h>

#define BB    4
#define NQ    2048
#define DIMK  1024
#define HEADS 16
#define DH    64
#define INNER 1024
#define NCOLS 3072
#define SPLIT 4

#define A_ELEMS (BB*NQ*INNER)
#define M_ELEMS (BB*HEADS*DH*DH)

__device__ __half g_qh[BB*HEADS*NQ*DH];
__device__ __half g_kh[BB*HEADS*NQ*DH];
__device__ __half g_vh[BB*HEADS*NQ*DH];
__device__ __half g_xh[BB*NQ*DIMK];
__device__ __half g_wh[DIMK*NCOLS];
__device__ float  g_mpart[BB*HEADS*SPLIT*DH*DH];
__device__ float  g_zpart[BB*HEADS*SPLIT*DH];
__device__ unsigned g_cnt[BB*HEADS];

__device__ __forceinline__ void mmah(float* c, const unsigned* a, const unsigned* b) {
    asm volatile(
        "mma.sync.aligned.m16n8k16.row.col.f32.f16.f16.f32 "
        "{%0,%1,%2,%3}, {%4,%5,%6,%7}, {%8,%9}, {%0,%1,%2,%3};\n"
        : "+f"(c[0]), "+f"(c[1]), "+f"(c[2]), "+f"(c[3])
        : "r"(a[0]), "r"(a[1]), "r"(a[2]), "r"(a[3]), "r"(b[0]), "r"(b[1]));
}
__device__ __forceinline__ void ldsm_x4(unsigned* r, unsigned addr) {
    asm volatile("ldmatrix.sync.aligned.m8n8.x4.shared.b16 {%0,%1,%2,%3}, [%4];"
        : "=r"(r[0]), "=r"(r[1]), "=r"(r[2]), "=r"(r[3]) : "r"(addr));
}
__device__ __forceinline__ void ldsm_x4_t(unsigned* r, unsigned addr) {
    asm volatile("ldmatrix.sync.aligned.m8n8.x4.trans.shared.b16 {%0,%1,%2,%3}, [%4];"
        : "=r"(r[0]), "=r"(r[1]), "=r"(r[2]), "=r"(r[3]) : "r"(addr));
}
__device__ __forceinline__ void ldsm_x2_t(unsigned* r, unsigned addr) {
    asm volatile("ldmatrix.sync.aligned.m8n8.x2.trans.shared.b16 {%0,%1}, [%2];"
        : "=r"(r[0]), "=r"(r[1]) : "r"(addr));
}
__device__ __forceinline__ unsigned packh2(float a, float b) {
    __half2 h = __floats2half2_rn(a, b);
    return *(unsigned*)&h;
}
__device__ __forceinline__ unsigned ex2h2(float a, float b) {
    unsigned p = packh2(a, b);
    unsigned r; asm("ex2.approx.f16x2 %0, %1;" : "=r"(r) : "r"(p));
    return r;
}
__device__ __forceinline__ float sigma_f(float f) {
    return (f > 0.f) ? (f + 1.f) : __expf(f);
}
__device__ __forceinline__ unsigned sptr(const void* p) {
    return (unsigned)__cvta_generic_to_shared(p);
}
#define CP16(dst, src) asm volatile("cp.async.ca.shared.global [%0], [%1], 16;" :: "r"(dst), "l"(src))
#define CP_COMMIT()    asm volatile("cp.async.commit_group;")
#define CP_WAIT0()     asm volatile("cp.async.wait_group 0;")
#define CP_WAIT1()     asm volatile("cp.async.wait_group 1;")

// ---------------------------------------------------------------------------
// Kernel 0: x, W -> half
// ---------------------------------------------------------------------------
__global__ __launch_bounds__(256)
void preconv(const float* __restrict__ x, const float* __restrict__ W) {
    const int nx = BB*NQ*DIMK/4;
    const int nw = DIMK*NCOLS/4;
    int i = blockIdx.x*256 + threadIdx.x;
    if (i < nx) {
        float4 v = ((const float4*)x)[i];
        ((__half2*)g_xh)[2*i]   = __floats2half2_rn(v.x, v.y);
        ((__half2*)g_xh)[2*i+1] = __floats2half2_rn(v.z, v.w);
    } else if (i < nx + nw) {
        int j = i - nx;
        float4 v = ((const float4*)W)[j];
        ((__half2*)g_wh)[2*j]   = __floats2half2_rn(v.x, v.y);
        ((__half2*)g_wh)[2*j+1] = __floats2half2_rn(v.z, v.w);
    }
}

// ---------------------------------------------------------------------------
// Kernel 1: QKV GEMM fp16 mma, BK=32, 3-stage cp.async pipeline (unchanged)
// ---------------------------------------------------------------------------
#define QA_STG (128*40)
#define QB_STG (32*136)
#define QKV_SMEM_BYTES ((3*QA_STG + 3*QB_STG)*2)

__global__ __launch_bounds__(256, 2)
void qkv_gemm(void) {
    extern __shared__ __align__(16) __half qsm[];
    __half* As = qsm;
    __half* Bs = qsm + 3*QA_STG;

    const int tid  = threadIdx.x;
    const int bm   = blockIdx.y * 128, bn = blockIdx.x * 128;
    const int wid  = tid >> 5, lane = tid & 31;
    const int wm   = (wid & 1) * 64, wn = (wid >> 1) * 32;
    const int lr   = lane >> 2, lc = lane & 3;

    const int ar = tid >> 2, ach = tid & 3;
    const int br = tid >> 4, bch = tid & 15;
    const __half* asrc0 = g_xh + (size_t)(bm + ar) * DIMK + ach*8;
    const __half* asrc1 = asrc0 + (size_t)64 * DIMK;
    const __half* bsrc0 = g_wh + (size_t)br * NCOLS + bn + bch*8;
    const __half* bsrc1 = bsrc0 + (size_t)16 * NCOLS;
    const unsigned a_off = sptr(&As[ar*40 + ach*8]);
    const unsigned b_off = sptr(&Bs[br*136 + bch*8]);

    #pragma unroll
    for (int s = 0; s < 2; ++s) {
        int ko = s * 32;
        CP16(a_off + s*QA_STG*2, asrc0 + ko);
        CP16(a_off + s*QA_STG*2 + 64*40*2, asrc1 + ko);
        CP16(b_off + s*QB_STG*2, bsrc0 + (size_t)ko * NCOLS);
        CP16(b_off + s*QB_STG*2 + 16*136*2, bsrc1 + (size_t)ko * NCOLS);
        CP_COMMIT();
    }

    float cacc[4][4][4];
    #pragma unroll
    for (int i = 0; i < 4; i++)
        #pragma unroll
        for (int j = 0; j < 4; j++) { cacc[i][j][0]=0.f; cacc[i][j][1]=0.f; cacc[i][j][2]=0.f; cacc[i][j][3]=0.f; }

    const int l15 = lane & 15;
    const int lhi8 = (lane & 16) >> 1;
    int cur = 0;
    for (int kt = 0; kt < DIMK/32; ++kt) {
        CP_WAIT1();
        __syncthreads();
        if (kt + 2 < DIMK/32) {
            int ko = (kt + 2) * 32;
            int nxs = (cur + 2) % 3;
            CP16(a_off + nxs*QA_STG*2, asrc0 + ko);
            CP16(a_off + nxs*QA_STG*2 + 64*40*2, asrc1 + ko);
            CP16(b_off + nxs*QB_STG*2, bsrc0 + (size_t)ko * NCOLS);
            CP16(b_off + nxs*QB_STG*2 + 16*136*2, bsrc1 + (size_t)ko * NCOLS);
            CP_COMMIT();
        }

        const __half* Ah = As + cur*QA_STG;
        const __half* Bh = Bs + cur*QB_STG;
        #pragma unroll
        for (int ks = 0; ks < 2; ++ks) {
            unsigned af[4][4];
            #pragma unroll
            for (int mt = 0; mt < 4; ++mt)
                ldsm_x4(af[mt], sptr(&Ah[(wm + mt*16 + l15)*40 + ks*16 + lhi8]));
            #pragma unroll
            for (int ntp = 0; ntp < 2; ++ntp) {
                unsigned bf[4];
                ldsm_x4_t(bf, sptr(&Bh[(ks*16 + l15)*136 + wn + ntp*16 + lhi8]));
                #pragma unroll
                for (int mt = 0; mt < 4; ++mt) {
                    mmah(cacc[mt][2*ntp],   af[mt], bf);
                    mmah(cacc[mt][2*ntp+1], af[mt], bf + 2);
                }
            }
        }
        cur = (cur + 1) % 3;
    }

    const int part = (bn + wn) >> 10;
    __half* dst = (part == 0) ? g_qh : (part == 1) ? g_kh : g_vh;
    #pragma unroll
    for (int mt = 0; mt < 4; ++mt) {
        int r0 = bm + wm + mt*16 + lr;
        #pragma unroll
        for (int nt = 0; nt < 4; ++nt) {
            int cg = bn + wn + nt*8 + 2*lc;
            int hh = (cg >> 6) & (HEADS - 1);
            int dd = cg & 63;
            int bi = r0 >> 11, nn = r0 & 2047;
            size_t off = (((size_t)(bi*HEADS + hh) * NQ + nn) * DH) + dd;
            int r1 = r0 + 8;
            int bi1 = r1 >> 11, nn1 = r1 & 2047;
            size_t off2 = (((size_t)(bi1*HEADS + hh) * NQ + nn1) * DH) + dd;
            *(unsigned*)&dst[off]  = packh2(cacc[mt][nt][0], cacc[mt][nt][1]);
            *(unsigned*)&dst[off2] = packh2(cacc[mt][nt][2], cacc[mt][nt][3]);
        }
    }
}

// ---------------------------------------------------------------------------
// Kernel 2: fp16 flash attention (R10 structure), Q pre-scaled by SCL2 so the
// tile loop needs no FMUL before exp. Raw Q reloaded for the memory branch.
// smem: KH[2][64*72] | VH[2][64*88] (col64 = ones) | Zs[64]
// ---------------------------------------------------------------------------
#define KTK (64*72)
#define KTV (64*88)
#define ATT_SMEM_BYTES ((2*KTK + 2*KTV)*2 + 64*4)
#define SCL2 0.1803368801111204f

__global__ __launch_bounds__(256, 2)
void attn_k(const float* __restrict__ M_in, const float* __restrict__ Z_in,
            const float* __restrict__ beta_gate, float* __restrict__ outA) {
    extern __shared__ __align__(16) __half smh[];
    __half* KH = smh;
    __half* VH = smh + 2*KTK;
    float*  Zs = (float*)(smh + 2*KTK + 2*KTV);

    const int tid = threadIdx.x, wid = tid >> 5, lane = tid & 31;
    const int lr = lane >> 2, lc = lane & 3;
    const int l15 = lane & 15;
    const int l7  = lane & 7;
    const int lhi8 = (lane & 16) >> 1;
    const int b = blockIdx.z, h = blockIdx.y, bh = b*HEADS + h;
    const int qb = blockIdx.x * 128;
    const int rowA = wid*16 + lr;

    const __half* qg = g_qh + ((size_t)bh*NQ + qb)*DH;
    const __half* kg = g_kh + (size_t)bh*NQ*DH;
    const __half* vg = g_vh + (size_t)bh*NQ*DH;

    const int cr = tid >> 3, cch = tid & 7;
    const unsigned k_off = sptr(&KH[cr*72 + cch*8]);
    const unsigned v_off = sptr(&VH[cr*88 + cch*8]);
    const __half* ksrc = kg + (size_t)cr*DH + cch*8;
    const __half* vsrc = vg + (size_t)cr*DH + cch*8;
    #define KROW32 (32*72*2)
    #define VROW32 (32*88*2)

    for (int i = tid; i < 128; i += 256) {
        int buf = i >> 6, r = i & 63;
        __half* vrow = VH + buf*KTV + r*88 + 64;
        vrow[0] = __float2half(1.f);
        #pragma unroll
        for (int c = 1; c < 8; ++c) vrow[c] = __float2half(0.f);
    }

    // Q fragments pre-scaled by SCL2 (S*SCL2 comes out of the mma directly)
    unsigned qa[4][4];
    #pragma unroll
    for (int ks = 0; ks < 4; ++ks) {
        #pragma unroll
        for (int p = 0; p < 4; ++p) {
            const __half* src = qg + (size_t)(rowA + (p & 1)*8)*DH + ks*16 + 2*lc + (p >> 1)*8;
            float2 f = __half22float2(*(const __half2*)src);
            qa[ks][p] = packh2(f.x*SCL2, f.y*SCL2);
        }
    }

    CP16(k_off, ksrc); CP16(k_off + KROW32, ksrc + 32*DH);
    CP16(v_off, vsrc); CP16(v_off + VROW32, vsrc + 32*DH);
    CP_COMMIT();

    float oacc[8][4];
    #pragma unroll
    for (int i = 0; i < 8; i++) { oacc[i][0]=0.f; oacc[i][1]=0.f; oacc[i][2]=0.f; oacc[i][3]=0.f; }
    float osum[4] = {0.f, 0.f, 0.f, 0.f};

    int cur = 0;
    for (int jt = 0; jt < NQ; jt += 64) {
        CP_WAIT0();
        __syncthreads();
        if (jt + 64 < NQ) {
            int nx = cur ^ 1;
            const __half* kn = ksrc + (size_t)(jt + 64)*DH;
            const __half* vn = vsrc + (size_t)(jt + 64)*DH;
            CP16(k_off + nx*KTK*2, kn); CP16(k_off + nx*KTK*2 + KROW32, kn + 32*DH);
            CP16(v_off + nx*KTV*2, vn); CP16(v_off + nx*KTV*2 + VROW32, vn + 32*DH);
            CP_COMMIT();
        }
        const __half* Kc = KH + cur*KTK;
        const __half* Vc = VH + cur*KTV;

        float sacc[8][4];
        #pragma unroll
        for (int i = 0; i < 8; i++) { sacc[i][0]=0.f; sacc[i][1]=0.f; sacc[i][2]=0.f; sacc[i][3]=0.f; }
        #pragma unroll
        for (int ks = 0; ks < 4; ++ks) {
            #pragma unroll
            for (int ntp = 0; ntp < 4; ++ntp) {
                unsigned kb[4];
                ldsm_x4(kb, sptr(&Kc[(ntp*16 + l7 + lhi8)*72 + ks*16 + (lane & 8)]));
                mmah(sacc[2*ntp],   qa[ks], kb);
                mmah(sacc[2*ntp+1], qa[ks], kb + 2);
            }
        }

        // P = exp2(sacc) directly (no scale needed)
        #pragma unroll
        for (int ks = 0; ks < 4; ++ks) {
            unsigned a[4];
            a[0] = ex2h2(sacc[2*ks][0],   sacc[2*ks][1]);
            a[1] = ex2h2(sacc[2*ks][2],   sacc[2*ks][3]);
            a[2] = ex2h2(sacc[2*ks+1][0], sacc[2*ks+1][1]);
            a[3] = ex2h2(sacc[2*ks+1][2], sacc[2*ks+1][3]);
            #pragma unroll
            for (int ntp = 0; ntp < 4; ++ntp) {
                unsigned vb[4];
                ldsm_x4_t(vb, sptr(&Vc[(ks*16 + l15)*88 + ntp*16 + lhi8]));
                mmah(oacc[2*ntp],   a, vb);
                mmah(oacc[2*ntp+1], a, vb + 2);
            }
            unsigned vs[2];
            ldsm_x2_t(vs, sptr(&Vc[(ks*16 + l15)*88 + 64]));
            mmah(osum, a, vs);
        }
        cur ^= 1;
    }

    float l1 = __shfl_sync(0xffffffffu, osum[0], lane & 28);
    float l2 = __shfl_sync(0xffffffffu, osum[2], lane & 28);

    // epilogue: reload RAW q, then A_mem = sigma(Q) @ M via fp16 mma
    __syncthreads();
    const float* Mg = M_in + (size_t)bh*DH*DH;
    __half* Mh = KH;
    for (int i = tid; i < DH*DH; i += 256) {
        int d = i >> 6, v = i & 63;
        Mh[d*72 + v] = __float2half_rn(Mg[i]);
    }
    if (tid < DH) Zs[tid] = Z_in[bh*DH + tid];
    __syncthreads();

    float macc[8][4];
    #pragma unroll
    for (int i = 0; i < 8; i++) { macc[i][0]=0.f; macc[i][1]=0.f; macc[i][2]=0.f; macc[i][3]=0.f; }
    float den1 = 0.f, den2 = 0.f;

    #pragma unroll
    for (int ks = 0; ks < 4; ++ks) {
        unsigned a[4];
        int c0 = ks*16 + 2*lc;
        float2 f0 = __half22float2(*(const __half2*)&qg[(size_t)rowA*DH + c0]);
        float2 f1 = __half22float2(*(const __half2*)&qg[(size_t)(rowA+8)*DH + c0]);
        float2 f2 = __half22float2(*(const __half2*)&qg[(size_t)rowA*DH + c0 + 8]);
        float2 f3 = __half22float2(*(const __half2*)&qg[(size_t)(rowA+8)*DH + c0 + 8]);
        float s00 = sigma_f(f0.x), s01 = sigma_f(f0.y);
        float s10 = sigma_f(f1.x), s11 = sigma_f(f1.y);
        float s20 = sigma_f(f2.x), s21 = sigma_f(f2.y);
        float s30 = sigma_f(f3.x), s31 = sigma_f(f3.y);
        a[0] = packh2(s00, s01); a[1] = packh2(s10, s11);
        a[2] = packh2(s20, s21); a[3] = packh2(s30, s31);
        den1 += s00*Zs[c0] + s01*Zs[c0+1] + s20*Zs[c0+8] + s21*Zs[c0+9];
        den2 += s10*Zs[c0] + s11*Zs[c0+1] + s30*Zs[c0+8] + s31*Zs[c0+9];
        #pragma unroll
        for (int ntp = 0; ntp < 4; ++ntp) {
            unsigned mb[4];
            ldsm_x4_t(mb, sptr(&Mh[(ks*16 + l15)*72 + ntp*16 + lhi8]));
            mmah(macc[2*ntp],   a, mb);
            mmah(macc[2*ntp+1], a, mb + 2);
        }
    }
    den1 += __shfl_xor_sync(0xffffffffu, den1, 1);
    den1 += __shfl_xor_sync(0xffffffffu, den1, 2);
    den2 += __shfl_xor_sync(0xffffffffu, den2, 1);
    den2 += __shfl_xor_sync(0xffffffffu, den2, 2);

    float g = 1.f / (1.f + __expf(-beta_gate[h]));
    float iv1 = 1.f/l1, iv2 = 1.f/l2, id1 = 1.f/den1, id2 = 1.f/den2;

    int n1 = qb + rowA;
    float* o1 = outA + ((size_t)(b*NQ + n1))*INNER + h*DH;
    float* o2 = o1 + (size_t)8*INNER;
    #pragma unroll
    for (int nt = 0; nt < 8; ++nt) {
        int d = nt*8 + 2*lc;
        *(float2*)&o1[d] = make_float2(
            g*macc[nt][0]*id1 + (1.f-g)*oacc[nt][0]*iv1,
            g*macc[nt][1]*id1 + (1.f-g)*oacc[nt][1]*iv1);
        *(float2*)&o2[d] = make_float2(
            g*macc[nt][2]*id2 + (1.f-g)*oacc[nt][2]*iv2,
            g*macc[nt][3]*id2 + (1.f-g)*oacc[nt][3]*iv2);
    }
}

// ---------------------------------------------------------------------------
// Kernel 3: state partials via fp16 mma + fused last-CTA reduction (unchanged)
// ---------------------------------------------------------------------------
#define ST_SMEM_BYTES ((3*64*72)*2 + 128*4)

__global__ __launch_bounds__(256)
void state_part(const float* __restrict__ M_in, const float* __restrict__ Z_in,
                const float* __restrict__ beta_lin, float* __restrict__ out) {
    extern __shared__ __align__(16) __half sst[];
    __half* Sksh = sst;
    __half* Vsh  = sst + 64*72;
    __half* Mth  = sst + 2*64*72;
    float*  Zs   = (float*)(sst + 3*64*72);
    float*  invden = Zs + 64;
    __shared__ unsigned slast;

    const int tid = threadIdx.x, wid = tid >> 5, lane = tid & 31;
    const int lr = lane >> 2, lc = lane & 3;
    const int l15 = lane & 15, l7 = lane & 7;
    const int lhi8 = (lane & 16) >> 1;
    const int bh = blockIdx.x >> 2;
    const int chunk = blockIdx.x & 3;
    const int nrows = NQ / SPLIT;
    const int rt = wid & 3, ct = wid >> 2;

    const float* Mg = M_in + (size_t)bh*DH*DH;
    for (int i = tid; i < DH*DH; i += 256) {
        int d = i >> 6, v = i & 63;
        Mth[v*72 + d] = __float2half_rn(Mg[i]);
    }
    if (tid < DH) Zs[tid] = Z_in[bh*DH + tid];

    const __half* kg = g_kh + ((size_t)bh*NQ + (size_t)chunk*nrows)*DH;
    const __half* vg = g_vh + ((size_t)bh*NQ + (size_t)chunk*nrows)*DH;

    float macc[4][4];
    #pragma unroll
    for (int i = 0; i < 4; i++) { macc[i][0]=0.f; macc[i][1]=0.f; macc[i][2]=0.f; macc[i][3]=0.f; }
    float zpart = 0.f;
    const int dz = wid*8 + lr;

    for (int n0 = 0; n0 < nrows; n0 += 64) {
        __syncthreads();
        #pragma unroll
        for (int t = 0; t < 2; ++t) {
            int c = tid + 256*t;
            int r = c >> 3, s8 = (c & 7) << 3;
            const __half2* kp = (const __half2*)&kg[(size_t)(n0+r)*DH + s8];
            __half2 h2[4];
            #pragma unroll
            for (int u = 0; u < 4; ++u) {
                float2 f = __half22float2(kp[u]);
                h2[u] = __floats2half2_rn(sigma_f(f.x), sigma_f(f.y));
            }
            *(uint4*)&Sksh[r*72 + s8] = *(uint4*)h2;
            *(uint4*)&Vsh[r*72 + s8] = *(const uint4*)&vg[(size_t)(n0+r)*DH + s8];
        }
        __syncthreads();

        {
            int rn = wid*8 + lr;
            float acc = 0.f;
            const __half2* sp = (const __half2*)&Sksh[rn*72 + lc*16];
            #pragma unroll
            for (int j = 0; j < 8; ++j) {
                float2 f = __half22float2(sp[j]);
                acc += f.x*Zs[lc*16 + 2*j] + f.y*Zs[lc*16 + 2*j + 1];
            }
            acc += __shfl_xor_sync(0xffffffffu, acc, 1);
            acc += __shfl_xor_sync(0xffffffffu, acc, 2);
            if (lc == 0) invden[rn] = 1.f / acc;
            #pragma unroll
            for (int j = 0; j < 16; ++j)
                zpart += __half2float(Sksh[(lc*16 + j)*72 + dz]);
        }
        __syncthreads();

        float pacc[4][4];
        #pragma unroll
        for (int i = 0; i < 4; i++) { pacc[i][0]=0.f; pacc[i][1]=0.f; pacc[i][2]=0.f; pacc[i][3]=0.f; }
        #pragma unroll
        for (int ks = 0; ks < 4; ++ks) {
            unsigned af[4];
            ldsm_x4(af, sptr(&Sksh[(rt*16 + l15)*72 + ks*16 + lhi8]));
            #pragma unroll
            for (int ntp = 0; ntp < 2; ++ntp) {
                unsigned bf[4];
                ldsm_x4(bf, sptr(&Mth[(ct*32 + ntp*16 + l7 + lhi8)*72 + ks*16 + (lane & 8)]));
                mmah(pacc[2*ntp],   af, bf);
                mmah(pacc[2*ntp+1], af, bf + 2);
            }
        }

        {
            int r0 = rt*16 + lr, r1 = r0 + 8;
            float iv0 = invden[r0], iv1 = invden[r1];
            #pragma unroll
            for (int nt = 0; nt < 4; ++nt) {
                int c0 = ct*32 + nt*8 + 2*lc;
                float2 fv0 = __half22float2(*(__half2*)&Vsh[r0*72 + c0]);
                *(__half2*)&Vsh[r0*72 + c0] =
                    __floats2half2_rn(fv0.x - pacc[nt][0]*iv0, fv0.y - pacc[nt][1]*iv0);
                float2 fv1 = __half22float2(*(__half2*)&Vsh[r1*72 + c0]);
                *(__half2*)&Vsh[r1*72 + c0] =
                    __floats2half2_rn(fv1.x - pacc[nt][2]*iv1, fv1.y - pacc[nt][3]*iv1);
            }
        }
        __syncthreads();

        #pragma unroll
        for (int ks = 0; ks < 4; ++ks) {
            unsigned a[4];
            ldsm_x4_t(a, sptr(&Sksh[(ks*16 + l7 + lhi8)*72 + rt*16 + (lane & 8)]));
            #pragma unroll
            for (int ntp = 0; ntp < 2; ++ntp) {
                unsigned bf[4];
                ldsm_x4_t(bf, sptr(&Vsh[(ks*16 + l15)*72 + ct*32 + ntp*16 + lhi8]));
                mmah(macc[2*ntp],   a, bf);
                mmah(macc[2*ntp+1], a, bf + 2);
            }
        }
    }

    float* mp = g_mpart + (size_t)blockIdx.x * DH*DH;
    int d0 = rt*16 + lr, d1 = d0 + 8;
    #pragma unroll
    for (int nt = 0; nt < 4; ++nt) {
        int c0 = ct*32 + nt*8 + 2*lc;
        *(float2*)&mp[d0*DH + c0] = make_float2(macc[nt][0], macc[nt][1]);
        *(float2*)&mp[d1*DH + c0] = make_float2(macc[nt][2], macc[nt][3]);
    }
    zpart += __shfl_xor_sync(0xffffffffu, zpart, 1);
    zpart += __shfl_xor_sync(0xffffffffu, zpart, 2);
    if (lc == 0) g_zpart[blockIdx.x*DH + dz] = zpart;

    __threadfence();
    if (tid == 0) slast = atomicInc(&g_cnt[bh], SPLIT - 1);
    __syncthreads();
    if (slast == SPLIT - 1) {
        float beta = 1.f / (1.f + __expf(-beta_lin[0]));
        beta = fminf(fmaxf(beta, 0.9f), 0.999f);
        float* mo = out + A_ELEMS + (size_t)bh*DH*DH;
        for (int e = tid; e < DH*DH; e += 256) {
            float s = beta*Mg[e];
            #pragma unroll
            for (int c = 0; c < SPLIT; ++c)
                s += g_mpart[(size_t)(bh*SPLIT + c)*DH*DH + e];
            mo[e] = s;
        }
        if (tid < DH) {
            float z = 0.f;
            #pragma unroll
            for (int c = 0; c < SPLIT; ++c)
                z += g_zpart[(bh*SPLIT + c)*DH + tid];
            out[A_ELEMS + M_ELEMS + bh*DH + tid] = beta*Z_in[bh*DH + tid] + z;
        }
    }
}

// ---------------------------------------------------------------------------
extern "C" void kernel_launch(void* const* d_in, const int* in_sizes, int n_in,
                              void* d_out, int out_size) {
    const float* x         = (const float*)d_in[0];
    const float* M         = (const float*)d_in[1];
    const float* Z         = (const float*)d_in[2];
    const float* W         = (const float*)d_in[3];
    const float* beta_lin  = (const float*)d_in[4];
    const float* beta_gate = (const float*)d_in[5];
    float* out = (float*)d_out;

    cudaFuncSetAttribute(qkv_gemm, cudaFuncAttributeMaxDynamicSharedMemorySize, QKV_SMEM_BYTES);
    cudaFuncSetAttribute(attn_k, cudaFuncAttributeMaxDynamicSharedMemorySize, ATT_SMEM_BYTES);
    cudaFuncSetAttribute(state_part, cudaFuncAttributeMaxDynamicSharedMemorySize, ST_SMEM_BYTES);

    const int npc = (BB*NQ*DIMK + DIMK*NCOLS)/4;
    preconv<<<(npc + 255)/256, 256>>>(x, W);
    qkv_gemm<<<dim3(NCOLS/128, (BB*NQ)/128), 256, QKV_SMEM_BYTES>>>();
    attn_k<<<dim3(NQ/128, HEADS, BB), 256, ATT_SMEM_BYTES>>>(M, Z, beta_gate, out);
    state_part<<<BB*HEADS*SPLIT, 256, ST_SMEM_BYTES>>>(M, Z, beta_lin, out);
}

// round 13
// speedup vs baseline: 1.0649x; 1.0091x over previous
#include <cuda_runtime.h>
#include <cuda_fp16.h>

#define BB    4
#define NQ    2048
#define DIMK  1024
#define HEADS 16
#define DH    64
#define INNER 1024
#define NCOLS 3072
#define SPLIT 8

#define A_ELEMS (BB*NQ*INNER)
#define M_ELEMS (BB*HEADS*DH*DH)

__device__ __half g_qh[BB*HEADS*NQ*DH];
__device__ __half g_kh[BB*HEADS*NQ*DH];
__device__ __half g_vh[BB*HEADS*NQ*DH];
__device__ __half g_xh[BB*NQ*DIMK];
__device__ __half g_wh[DIMK*NCOLS];
__device__ float  g_mpart[BB*HEADS*SPLIT*DH*DH];
__device__ float  g_zpart[BB*HEADS*SPLIT*DH];
__device__ unsigned g_cnt[BB*HEADS];

__device__ __forceinline__ void mmah(float* c, const unsigned* a, const unsigned* b) {
    asm volatile(
        "mma.sync.aligned.m16n8k16.row.col.f32.f16.f16.f32 "
        "{%0,%1,%2,%3}, {%4,%5,%6,%7}, {%8,%9}, {%0,%1,%2,%3};\n"
        : "+f"(c[0]), "+f"(c[1]), "+f"(c[2]), "+f"(c[3])
        : "r"(a[0]), "r"(a[1]), "r"(a[2]), "r"(a[3]), "r"(b[0]), "r"(b[1]));
}
__device__ __forceinline__ void ldsm_x4(unsigned* r, unsigned addr) {
    asm volatile("ldmatrix.sync.aligned.m8n8.x4.shared.b16 {%0,%1,%2,%3}, [%4];"
        : "=r"(r[0]), "=r"(r[1]), "=r"(r[2]), "=r"(r[3]) : "r"(addr));
}
__device__ __forceinline__ void ldsm_x4_t(unsigned* r, unsigned addr) {
    asm volatile("ldmatrix.sync.aligned.m8n8.x4.trans.shared.b16 {%0,%1,%2,%3}, [%4];"
        : "=r"(r[0]), "=r"(r[1]), "=r"(r[2]), "=r"(r[3]) : "r"(addr));
}
__device__ __forceinline__ void ldsm_x2_t(unsigned* r, unsigned addr) {
    asm volatile("ldmatrix.sync.aligned.m8n8.x2.trans.shared.b16 {%0,%1}, [%2];"
        : "=r"(r[0]), "=r"(r[1]) : "r"(addr));
}
__device__ __forceinline__ unsigned packh2(float a, float b) {
    __half2 h = __floats2half2_rn(a, b);
    return *(unsigned*)&h;
}
__device__ __forceinline__ unsigned ex2h2(float a, float b) {
    unsigned p = packh2(a, b);
    unsigned r; asm("ex2.approx.f16x2 %0, %1;" : "=r"(r) : "r"(p));
    return r;
}
__device__ __forceinline__ float sigma_f(float f) {
    return (f > 0.f) ? (f + 1.f) : __expf(f);
}
__device__ __forceinline__ unsigned sptr(const void* p) {
    return (unsigned)__cvta_generic_to_shared(p);
}
#define CP16(dst, src) asm volatile("cp.async.ca.shared.global [%0], [%1], 16;" :: "r"(dst), "l"(src))
#define CP_COMMIT()    asm volatile("cp.async.commit_group;")
#define CP_WAIT0()     asm volatile("cp.async.wait_group 0;")
#define CP_WAIT1()     asm volatile("cp.async.wait_group 1;")

// ---------------------------------------------------------------------------
// Kernel 0: x, W -> half
// ---------------------------------------------------------------------------
__global__ __launch_bounds__(256)
void preconv(const float* __restrict__ x, const float* __restrict__ W) {
    const int nx = BB*NQ*DIMK/4;
    const int nw = DIMK*NCOLS/4;
    int i = blockIdx.x*256 + threadIdx.x;
    if (i < nx) {
        float4 v = ((const float4*)x)[i];
        ((__half2*)g_xh)[2*i]   = __floats2half2_rn(v.x, v.y);
        ((__half2*)g_xh)[2*i+1] = __floats2half2_rn(v.z, v.w);
    } else if (i < nx + nw) {
        int j = i - nx;
        float4 v = ((const float4*)W)[j];
        ((__half2*)g_wh)[2*j]   = __floats2half2_rn(v.x, v.y);
        ((__half2*)g_wh)[2*j+1] = __floats2half2_rn(v.z, v.w);
    }
}

// ---------------------------------------------------------------------------
// Kernel 1: QKV GEMM fp16 mma, BK=32, 3-stage cp.async pipeline (unchanged)
// ---------------------------------------------------------------------------
#define QA_STG (128*40)
#define QB_STG (32*136)
#define QKV_SMEM_BYTES ((3*QA_STG + 3*QB_STG)*2)

__global__ __launch_bounds__(256, 2)
void qkv_gemm(void) {
    extern __shared__ __align__(16) __half qsm[];
    __half* As = qsm;
    __half* Bs = qsm + 3*QA_STG;

    const int tid  = threadIdx.x;
    const int bm   = blockIdx.y * 128, bn = blockIdx.x * 128;
    const int wid  = tid >> 5, lane = tid & 31;
    const int wm   = (wid & 1) * 64, wn = (wid >> 1) * 32;
    const int lr   = lane >> 2, lc = lane & 3;

    const int ar = tid >> 2, ach = tid & 3;
    const int br = tid >> 4, bch = tid & 15;
    const __half* asrc0 = g_xh + (size_t)(bm + ar) * DIMK + ach*8;
    const __half* asrc1 = asrc0 + (size_t)64 * DIMK;
    const __half* bsrc0 = g_wh + (size_t)br * NCOLS + bn + bch*8;
    const __half* bsrc1 = bsrc0 + (size_t)16 * NCOLS;
    const unsigned a_off = sptr(&As[ar*40 + ach*8]);
    const unsigned b_off = sptr(&Bs[br*136 + bch*8]);

    #pragma unroll
    for (int s = 0; s < 2; ++s) {
        int ko = s * 32;
        CP16(a_off + s*QA_STG*2, asrc0 + ko);
        CP16(a_off + s*QA_STG*2 + 64*40*2, asrc1 + ko);
        CP16(b_off + s*QB_STG*2, bsrc0 + (size_t)ko * NCOLS);
        CP16(b_off + s*QB_STG*2 + 16*136*2, bsrc1 + (size_t)ko * NCOLS);
        CP_COMMIT();
    }

    float cacc[4][4][4];
    #pragma unroll
    for (int i = 0; i < 4; i++)
        #pragma unroll
        for (int j = 0; j < 4; j++) { cacc[i][j][0]=0.f; cacc[i][j][1]=0.f; cacc[i][j][2]=0.f; cacc[i][j][3]=0.f; }

    const int l15 = lane & 15;
    const int lhi8 = (lane & 16) >> 1;
    int cur = 0;
    for (int kt = 0; kt < DIMK/32; ++kt) {
        CP_WAIT1();
        __syncthreads();
        if (kt + 2 < DIMK/32) {
            int ko = (kt + 2) * 32;
            int nxs = (cur + 2) % 3;
            CP16(a_off + nxs*QA_STG*2, asrc0 + ko);
            CP16(a_off + nxs*QA_STG*2 + 64*40*2, asrc1 + ko);
            CP16(b_off + nxs*QB_STG*2, bsrc0 + (size_t)ko * NCOLS);
            CP16(b_off + nxs*QB_STG*2 + 16*136*2, bsrc1 + (size_t)ko * NCOLS);
            CP_COMMIT();
        }

        const __half* Ah = As + cur*QA_STG;
        const __half* Bh = Bs + cur*QB_STG;
        #pragma unroll
        for (int ks = 0; ks < 2; ++ks) {
            unsigned af[4][4];
            #pragma unroll
            for (int mt = 0; mt < 4; ++mt)
                ldsm_x4(af[mt], sptr(&Ah[(wm + mt*16 + l15)*40 + ks*16 + lhi8]));
            #pragma unroll
            for (int ntp = 0; ntp < 2; ++ntp) {
                unsigned bf[4];
                ldsm_x4_t(bf, sptr(&Bh[(ks*16 + l15)*136 + wn + ntp*16 + lhi8]));
                #pragma unroll
                for (int mt = 0; mt < 4; ++mt) {
                    mmah(cacc[mt][2*ntp],   af[mt], bf);
                    mmah(cacc[mt][2*ntp+1], af[mt], bf + 2);
                }
            }
        }
        cur = (cur + 1) % 3;
    }

    const int part = (bn + wn) >> 10;
    __half* dst = (part == 0) ? g_qh : (part == 1) ? g_kh : g_vh;
    #pragma unroll
    for (int mt = 0; mt < 4; ++mt) {
        int r0 = bm + wm + mt*16 + lr;
        #pragma unroll
        for (int nt = 0; nt < 4; ++nt) {
            int cg = bn + wn + nt*8 + 2*lc;
            int hh = (cg >> 6) & (HEADS - 1);
            int dd = cg & 63;
            int bi = r0 >> 11, nn = r0 & 2047;
            size_t off = (((size_t)(bi*HEADS + hh) * NQ + nn) * DH) + dd;
            int r1 = r0 + 8;
            int bi1 = r1 >> 11, nn1 = r1 & 2047;
            size_t off2 = (((size_t)(bi1*HEADS + hh) * NQ + nn1) * DH) + dd;
            *(unsigned*)&dst[off]  = packh2(cacc[mt][nt][0], cacc[mt][nt][1]);
            *(unsigned*)&dst[off2] = packh2(cacc[mt][nt][2], cacc[mt][nt][3]);
        }
    }
}

// ---------------------------------------------------------------------------
// Kernel 2: fp16 flash attention (unchanged from R12)
// ---------------------------------------------------------------------------
#define KTK (64*72)
#define KTV (64*88)
#define ATT_SMEM_BYTES ((2*KTK + 2*KTV)*2 + 64*4)
#define SCL2 0.1803368801111204f

__global__ __launch_bounds__(256, 2)
void attn_k(const float* __restrict__ M_in, const float* __restrict__ Z_in,
            const float* __restrict__ beta_gate, float* __restrict__ outA) {
    extern __shared__ __align__(16) __half smh[];
    __half* KH = smh;
    __half* VH = smh + 2*KTK;
    float*  Zs = (float*)(smh + 2*KTK + 2*KTV);

    const int tid = threadIdx.x, wid = tid >> 5, lane = tid & 31;
    const int lr = lane >> 2, lc = lane & 3;
    const int l15 = lane & 15;
    const int l7  = lane & 7;
    const int lhi8 = (lane & 16) >> 1;
    const int b = blockIdx.z, h = blockIdx.y, bh = b*HEADS + h;
    const int qb = blockIdx.x * 128;
    const int rowA = wid*16 + lr;

    const __half* qg = g_qh + ((size_t)bh*NQ + qb)*DH;
    const __half* kg = g_kh + (size_t)bh*NQ*DH;
    const __half* vg = g_vh + (size_t)bh*NQ*DH;

    const int cr = tid >> 3, cch = tid & 7;
    const unsigned k_off = sptr(&KH[cr*72 + cch*8]);
    const unsigned v_off = sptr(&VH[cr*88 + cch*8]);
    const __half* ksrc = kg + (size_t)cr*DH + cch*8;
    const __half* vsrc = vg + (size_t)cr*DH + cch*8;
    #define KROW32 (32*72*2)
    #define VROW32 (32*88*2)

    for (int i = tid; i < 128; i += 256) {
        int buf = i >> 6, r = i & 63;
        __half* vrow = VH + buf*KTV + r*88 + 64;
        vrow[0] = __float2half(1.f);
        #pragma unroll
        for (int c = 1; c < 8; ++c) vrow[c] = __float2half(0.f);
    }

    // Q fragments pre-scaled by SCL2
    unsigned qa[4][4];
    #pragma unroll
    for (int ks = 0; ks < 4; ++ks) {
        #pragma unroll
        for (int p = 0; p < 4; ++p) {
            const __half* src = qg + (size_t)(rowA + (p & 1)*8)*DH + ks*16 + 2*lc + (p >> 1)*8;
            float2 f = __half22float2(*(const __half2*)src);
            qa[ks][p] = packh2(f.x*SCL2, f.y*SCL2);
        }
    }

    CP16(k_off, ksrc); CP16(k_off + KROW32, ksrc + 32*DH);
    CP16(v_off, vsrc); CP16(v_off + VROW32, vsrc + 32*DH);
    CP_COMMIT();

    float oacc[8][4];
    #pragma unroll
    for (int i = 0; i < 8; i++) { oacc[i][0]=0.f; oacc[i][1]=0.f; oacc[i][2]=0.f; oacc[i][3]=0.f; }
    float osum[4] = {0.f, 0.f, 0.f, 0.f};

    int cur = 0;
    for (int jt = 0; jt < NQ; jt += 64) {
        CP_WAIT0();
        __syncthreads();
        if (jt + 64 < NQ) {
            int nx = cur ^ 1;
            const __half* kn = ksrc + (size_t)(jt + 64)*DH;
            const __half* vn = vsrc + (size_t)(jt + 64)*DH;
            CP16(k_off + nx*KTK*2, kn); CP16(k_off + nx*KTK*2 + KROW32, kn + 32*DH);
            CP16(v_off + nx*KTV*2, vn); CP16(v_off + nx*KTV*2 + VROW32, vn + 32*DH);
            CP_COMMIT();
        }
        const __half* Kc = KH + cur*KTK;
        const __half* Vc = VH + cur*KTV;

        float sacc[8][4];
        #pragma unroll
        for (int i = 0; i < 8; i++) { sacc[i][0]=0.f; sacc[i][1]=0.f; sacc[i][2]=0.f; sacc[i][3]=0.f; }
        #pragma unroll
        for (int ks = 0; ks < 4; ++ks) {
            #pragma unroll
            for (int ntp = 0; ntp < 4; ++ntp) {
                unsigned kb[4];
                ldsm_x4(kb, sptr(&Kc[(ntp*16 + l7 + lhi8)*72 + ks*16 + (lane & 8)]));
                mmah(sacc[2*ntp],   qa[ks], kb);
                mmah(sacc[2*ntp+1], qa[ks], kb + 2);
            }
        }

        #pragma unroll
        for (int ks = 0; ks < 4; ++ks) {
            unsigned a[4];
            a[0] = ex2h2(sacc[2*ks][0],   sacc[2*ks][1]);
            a[1] = ex2h2(sacc[2*ks][2],   sacc[2*ks][3]);
            a[2] = ex2h2(sacc[2*ks+1][0], sacc[2*ks+1][1]);
            a[3] = ex2h2(sacc[2*ks+1][2], sacc[2*ks+1][3]);
            #pragma unroll
            for (int ntp = 0; ntp < 4; ++ntp) {
                unsigned vb[4];
                ldsm_x4_t(vb, sptr(&Vc[(ks*16 + l15)*88 + ntp*16 + lhi8]));
                mmah(oacc[2*ntp],   a, vb);
                mmah(oacc[2*ntp+1], a, vb + 2);
            }
            unsigned vs[2];
            ldsm_x2_t(vs, sptr(&Vc[(ks*16 + l15)*88 + 64]));
            mmah(osum, a, vs);
        }
        cur ^= 1;
    }

    float l1 = __shfl_sync(0xffffffffu, osum[0], lane & 28);
    float l2 = __shfl_sync(0xffffffffu, osum[2], lane & 28);

    __syncthreads();
    const float* Mg = M_in + (size_t)bh*DH*DH;
    __half* Mh = KH;
    for (int i = tid; i < DH*DH; i += 256) {
        int d = i >> 6, v = i & 63;
        Mh[d*72 + v] = __float2half_rn(Mg[i]);
    }
    if (tid < DH) Zs[tid] = Z_in[bh*DH + tid];
    __syncthreads();

    float macc[8][4];
    #pragma unroll
    for (int i = 0; i < 8; i++) { macc[i][0]=0.f; macc[i][1]=0.f; macc[i][2]=0.f; macc[i][3]=0.f; }
    float den1 = 0.f, den2 = 0.f;

    #pragma unroll
    for (int ks = 0; ks < 4; ++ks) {
        unsigned a[4];
        int c0 = ks*16 + 2*lc;
        float2 f0 = __half22float2(*(const __half2*)&qg[(size_t)rowA*DH + c0]);
        float2 f1 = __half22float2(*(const __half2*)&qg[(size_t)(rowA+8)*DH + c0]);
        float2 f2 = __half22float2(*(const __half2*)&qg[(size_t)rowA*DH + c0 + 8]);
        float2 f3 = __half22float2(*(const __half2*)&qg[(size_t)(rowA+8)*DH + c0 + 8]);
        float s00 = sigma_f(f0.x), s01 = sigma_f(f0.y);
        float s10 = sigma_f(f1.x), s11 = sigma_f(f1.y);
        float s20 = sigma_f(f2.x), s21 = sigma_f(f2.y);
        float s30 = sigma_f(f3.x), s31 = sigma_f(f3.y);
        a[0] = packh2(s00, s01); a[1] = packh2(s10, s11);
        a[2] = packh2(s20, s21); a[3] = packh2(s30, s31);
        den1 += s00*Zs[c0] + s01*Zs[c0+1] + s20*Zs[c0+8] + s21*Zs[c0+9];
        den2 += s10*Zs[c0] + s11*Zs[c0+1] + s30*Zs[c0+8] + s31*Zs[c0+9];
        #pragma unroll
        for (int ntp = 0; ntp < 4; ++ntp) {
            unsigned mb[4];
            ldsm_x4_t(mb, sptr(&Mh[(ks*16 + l15)*72 + ntp*16 + lhi8]));
            mmah(macc[2*ntp],   a, mb);
            mmah(macc[2*ntp+1], a, mb + 2);
        }
    }
    den1 += __shfl_xor_sync(0xffffffffu, den1, 1);
    den1 += __shfl_xor_sync(0xffffffffu, den1, 2);
    den2 += __shfl_xor_sync(0xffffffffu, den2, 1);
    den2 += __shfl_xor_sync(0xffffffffu, den2, 2);

    float g = 1.f / (1.f + __expf(-beta_gate[h]));
    float iv1 = 1.f/l1, iv2 = 1.f/l2, id1 = 1.f/den1, id2 = 1.f/den2;

    int n1 = qb + rowA;
    float* o1 = outA + ((size_t)(b*NQ + n1))*INNER + h*DH;
    float* o2 = o1 + (size_t)8*INNER;
    #pragma unroll
    for (int nt = 0; nt < 8; ++nt) {
        int d = nt*8 + 2*lc;
        *(float2*)&o1[d] = make_float2(
            g*macc[nt][0]*id1 + (1.f-g)*oacc[nt][0]*iv1,
            g*macc[nt][1]*id1 + (1.f-g)*oacc[nt][1]*iv1);
        *(float2*)&o2[d] = make_float2(
            g*macc[nt][2]*id2 + (1.f-g)*oacc[nt][2]*iv2,
            g*macc[nt][3]*id2 + (1.f-g)*oacc[nt][3]*iv2);
    }
}

// ---------------------------------------------------------------------------
// Kernel 3: state partials via fp16 mma + fused last-CTA reduction, SPLIT=8
// ---------------------------------------------------------------------------
#define ST_SMEM_BYTES ((3*64*72)*2 + 128*4)

__global__ __launch_bounds__(256)
void state_part(const float* __restrict__ M_in, const float* __restrict__ Z_in,
                const float* __restrict__ beta_lin, float* __restrict__ out) {
    extern __shared__ __align__(16) __half sst[];
    __half* Sksh = sst;
    __half* Vsh  = sst + 64*72;
    __half* Mth  = sst + 2*64*72;
    float*  Zs   = (float*)(sst + 3*64*72);
    float*  invden = Zs + 64;
    __shared__ unsigned slast;

    const int tid = threadIdx.x, wid = tid >> 5, lane = tid & 31;
    const int lr = lane >> 2, lc = lane & 3;
    const int l15 = lane & 15, l7 = lane & 7;
    const int lhi8 = (lane & 16) >> 1;
    const int bh = blockIdx.x >> 3;
    const int chunk = blockIdx.x & 7;
    const int nrows = NQ / SPLIT;
    const int rt = wid & 3, ct = wid >> 2;

    const float* Mg = M_in + (size_t)bh*DH*DH;
    for (int i = tid; i < DH*DH; i += 256) {
        int d = i >> 6, v = i & 63;
        Mth[v*72 + d] = __float2half_rn(Mg[i]);
    }
    if (tid < DH) Zs[tid] = Z_in[bh*DH + tid];

    const __half* kg = g_kh + ((size_t)bh*NQ + (size_t)chunk*nrows)*DH;
    const __half* vg = g_vh + ((size_t)bh*NQ + (size_t)chunk*nrows)*DH;

    float macc[4][4];
    #pragma unroll
    for (int i = 0; i < 4; i++) { macc[i][0]=0.f; macc[i][1]=0.f; macc[i][2]=0.f; macc[i][3]=0.f; }
    float zpart = 0.f;
    const int dz = wid*8 + lr;

    for (int n0 = 0; n0 < nrows; n0 += 64) {
        __syncthreads();
        #pragma unroll
        for (int t = 0; t < 2; ++t) {
            int c = tid + 256*t;
            int r = c >> 3, s8 = (c & 7) << 3;
            const __half2* kp = (const __half2*)&kg[(size_t)(n0+r)*DH + s8];
            __half2 h2[4];
            #pragma unroll
            for (int u = 0; u < 4; ++u) {
                float2 f = __half22float2(kp[u]);
                h2[u] = __floats2half2_rn(sigma_f(f.x), sigma_f(f.y));
            }
            *(uint4*)&Sksh[r*72 + s8] = *(uint4*)h2;
            *(uint4*)&Vsh[r*72 + s8] = *(const uint4*)&vg[(size_t)(n0+r)*DH + s8];
        }
        __syncthreads();

        {
            int rn = wid*8 + lr;
            float acc = 0.f;
            const __half2* sp = (const __half2*)&Sksh[rn*72 + lc*16];
            #pragma unroll
            for (int j = 0; j < 8; ++j) {
                float2 f = __half22float2(sp[j]);
                acc += f.x*Zs[lc*16 + 2*j] + f.y*Zs[lc*16 + 2*j + 1];
            }
            acc += __shfl_xor_sync(0xffffffffu, acc, 1);
            acc += __shfl_xor_sync(0xffffffffu, acc, 2);
            if (lc == 0) invden[rn] = 1.f / acc;
            #pragma unroll
            for (int j = 0; j < 16; ++j)
                zpart += __half2float(Sksh[(lc*16 + j)*72 + dz]);
        }
        __syncthreads();

        float pacc[4][4];
        #pragma unroll
        for (int i = 0; i < 4; i++) { pacc[i][0]=0.f; pacc[i][1]=0.f; pacc[i][2]=0.f; pacc[i][3]=0.f; }
        #pragma unroll
        for (int ks = 0; ks < 4; ++ks) {
            unsigned af[4];
            ldsm_x4(af, sptr(&Sksh[(rt*16 + l15)*72 + ks*16 + lhi8]));
            #pragma unroll
            for (int ntp = 0; ntp < 2; ++ntp) {
                unsigned bf[4];
                ldsm_x4(bf, sptr(&Mth[(ct*32 + ntp*16 + l7 + lhi8)*72 + ks*16 + (lane & 8)]));
                mmah(pacc[2*ntp],   af, bf);
                mmah(pacc[2*ntp+1], af, bf + 2);
            }
        }

        {
            int r0 = rt*16 + lr, r1 = r0 + 8;
            float iv0 = invden[r0], iv1 = invden[r1];
            #pragma unroll
            for (int nt = 0; nt < 4; ++nt) {
                int c0 = ct*32 + nt*8 + 2*lc;
                float2 fv0 = __half22float2(*(__half2*)&Vsh[r0*72 + c0]);
                *(__half2*)&Vsh[r0*72 + c0] =
                    __floats2half2_rn(fv0.x - pacc[nt][0]*iv0, fv0.y - pacc[nt][1]*iv0);
                float2 fv1 = __half22float2(*(__half2*)&Vsh[r1*72 + c0]);
                *(__half2*)&Vsh[r1*72 + c0] =
                    __floats2half2_rn(fv1.x - pacc[nt][2]*iv1, fv1.y - pacc[nt][3]*iv1);
            }
        }
        __syncthreads();

        #pragma unroll
        for (int ks = 0; ks < 4; ++ks) {
            unsigned a[4];
            ldsm_x4_t(a, sptr(&Sksh[(ks*16 + l7 + lhi8)*72 + rt*16 + (lane & 8)]));
            #pragma unroll
            for (int ntp = 0; ntp < 2; ++ntp) {
                unsigned bf[4];
                ldsm_x4_t(bf, sptr(&Vsh[(ks*16 + l15)*72 + ct*32 + ntp*16 + lhi8]));
                mmah(macc[2*ntp],   a, bf);
                mmah(macc[2*ntp+1], a, bf + 2);
            }
        }
    }

    float* mp = g_mpart + (size_t)blockIdx.x * DH*DH;
    int d0 = rt*16 + lr, d1 = d0 + 8;
    #pragma unroll
    for (int nt = 0; nt < 4; ++nt) {
        int c0 = ct*32 + nt*8 + 2*lc;
        *(float2*)&mp[d0*DH + c0] = make_float2(macc[nt][0], macc[nt][1]);
        *(float2*)&mp[d1*DH + c0] = make_float2(macc[nt][2], macc[nt][3]);
    }
    zpart += __shfl_xor_sync(0xffffffffu, zpart, 1);
    zpart += __shfl_xor_sync(0xffffffffu, zpart, 2);
    if (lc == 0) g_zpart[blockIdx.x*DH + dz] = zpart;

    __threadfence();
    if (tid == 0) slast = atomicInc(&g_cnt[bh], SPLIT - 1);
    __syncthreads();
    if (slast == SPLIT - 1) {
        float beta = 1.f / (1.f + __expf(-beta_lin[0]));
        beta = fminf(fmaxf(beta, 0.9f), 0.999f);
        float* mo = out + A_ELEMS + (size_t)bh*DH*DH;
        for (int e = tid; e < DH*DH; e += 256) {
            float s = beta*Mg[e];
            #pragma unroll
            for (int c = 0; c < SPLIT; ++c)
                s += g_mpart[(size_t)(bh*SPLIT + c)*DH*DH + e];
            mo[e] = s;
        }
        if (tid < DH) {
            float z = 0.f;
            #pragma unroll
            for (int c = 0; c < SPLIT; ++c)
                z += g_zpart[(bh*SPLIT + c)*DH + tid];
            out[A_ELEMS + M_ELEMS + bh*DH + tid] = beta*Z_in[bh*DH + tid] + z;
        }
    }
}

// ---------------------------------------------------------------------------
extern "C" void kernel_launch(void* const* d_in, const int* in_sizes, int n_in,
                              void* d_out, int out_size) {
    const float* x         = (const float*)d_in[0];
    const float* M         = (const float*)d_in[1];
    const float* Z         = (const float*)d_in[2];
    const float* W         = (const float*)d_in[3];
    const float* beta_lin  = (const float*)d_in[4];
    const float* beta_gate = (const float*)d_in[5];
    float* out = (float*)d_out;

    cudaFuncSetAttribute(qkv_gemm, cudaFuncAttributeMaxDynamicSharedMemorySize, QKV_SMEM_BYTES);
    cudaFuncSetAttribute(attn_k, cudaFuncAttributeMaxDynamicSharedMemorySize, ATT_SMEM_BYTES);
    cudaFuncSetAttribute(state_part, cudaFuncAttributeMaxDynamicSharedMemorySize, ST_SMEM_BYTES);

    const int npc = (BB*NQ*DIMK + DIMK*NCOLS)/4;
    preconv<<<(npc + 255)/256, 256>>>(x, W);
    qkv_gemm<<<dim3(NCOLS/128, (BB*NQ)/128), 256, QKV_SMEM_BYTES>>>();
    attn_k<<<dim3(NQ/128, HEADS, BB), 256, ATT_SMEM_BYTES>>>(M, Z, beta_gate, out);
    state_part<<<BB*HEADS*SPLIT, 256, ST_SMEM_BYTES>>>(M, Z, beta_lin, out);
}

// round 14
// speedup vs baseline: 1.0813x; 1.0154x over previous
#include <cuda_runtime.h>
#include <cuda_fp16.h>

#define BB    4
#define NQ    2048
#define DIMK  1024
#define HEADS 16
#define DH    64
#define INNER 1024
#define NCOLS 3072
#define SPLIT 8

#define A_ELEMS (BB*NQ*INNER)
#define M_ELEMS (BB*HEADS*DH*DH)

__device__ __half g_qh[BB*HEADS*NQ*DH];
__device__ __half g_kh[BB*HEADS*NQ*DH];
__device__ __half g_vh[BB*HEADS*NQ*DH];
__device__ __half g_xh[BB*NQ*DIMK];
__device__ __half g_wh[DIMK*NCOLS];
__device__ float  g_mpart[BB*HEADS*SPLIT*DH*DH];
__device__ float  g_zpart[BB*HEADS*SPLIT*DH];
__device__ unsigned g_cnt[BB*HEADS];

__device__ __forceinline__ void mmah(float* c, const unsigned* a, const unsigned* b) {
    asm volatile(
        "mma.sync.aligned.m16n8k16.row.col.f32.f16.f16.f32 "
        "{%0,%1,%2,%3}, {%4,%5,%6,%7}, {%8,%9}, {%0,%1,%2,%3};\n"
        : "+f"(c[0]), "+f"(c[1]), "+f"(c[2]), "+f"(c[3])
        : "r"(a[0]), "r"(a[1]), "r"(a[2]), "r"(a[3]), "r"(b[0]), "r"(b[1]));
}
__device__ __forceinline__ void ldsm_x4(unsigned* r, unsigned addr) {
    asm volatile("ldmatrix.sync.aligned.m8n8.x4.shared.b16 {%0,%1,%2,%3}, [%4];"
        : "=r"(r[0]), "=r"(r[1]), "=r"(r[2]), "=r"(r[3]) : "r"(addr));
}
__device__ __forceinline__ void ldsm_x4_t(unsigned* r, unsigned addr) {
    asm volatile("ldmatrix.sync.aligned.m8n8.x4.trans.shared.b16 {%0,%1,%2,%3}, [%4];"
        : "=r"(r[0]), "=r"(r[1]), "=r"(r[2]), "=r"(r[3]) : "r"(addr));
}
__device__ __forceinline__ void ldsm_x2_t(unsigned* r, unsigned addr) {
    asm volatile("ldmatrix.sync.aligned.m8n8.x2.trans.shared.b16 {%0,%1}, [%2];"
        : "=r"(r[0]), "=r"(r[1]) : "r"(addr));
}
__device__ __forceinline__ unsigned packh2(float a, float b) {
    __half2 h = __floats2half2_rn(a, b);
    return *(unsigned*)&h;
}
__device__ __forceinline__ unsigned ex2h2(float a, float b) {
    unsigned p = packh2(a, b);
    unsigned r; asm("ex2.approx.f16x2 %0, %1;" : "=r"(r) : "r"(p));
    return r;
}
__device__ __forceinline__ float sigma_f(float f) {
    return (f > 0.f) ? (f + 1.f) : __expf(f);
}
__device__ __forceinline__ unsigned sptr(const void* p) {
    return (unsigned)__cvta_generic_to_shared(p);
}
#define CP16(dst, src) asm volatile("cp.async.ca.shared.global [%0], [%1], 16;" :: "r"(dst), "l"(src))
#define CP_COMMIT()    asm volatile("cp.async.commit_group;")
#define CP_WAIT0()     asm volatile("cp.async.wait_group 0;")
#define CP_WAIT1()     asm volatile("cp.async.wait_group 1;")

// ---------------------------------------------------------------------------
// Kernel 0: x, W -> half (4 independent float4 loads per thread, MLP=4)
// ---------------------------------------------------------------------------
__global__ __launch_bounds__(256)
void preconv(const float* __restrict__ x, const float* __restrict__ W) {
    const int nx = BB*NQ*DIMK/4;
    const int nw = DIMK*NCOLS/4;
    const int base = blockIdx.x*1024 + threadIdx.x;
    float4 vv[4];
    uint2* dd[4];
    #pragma unroll
    for (int t = 0; t < 4; ++t) {
        int i = base + t*256;
        bool valid = (i < nx + nw);
        bool isx = (i < nx);
        const float4* sp = isx ? ((const float4*)x) + i : ((const float4*)W) + (i - nx);
        dd[t] = valid ? (isx ? ((uint2*)g_xh) + i : ((uint2*)g_wh) + (i - nx)) : nullptr;
        if (valid) vv[t] = *sp;
    }
    #pragma unroll
    for (int t = 0; t < 4; ++t) {
        if (dd[t]) *dd[t] = make_uint2(packh2(vv[t].x, vv[t].y), packh2(vv[t].z, vv[t].w));
    }
}

// ---------------------------------------------------------------------------
// Kernel 1: QKV GEMM fp16 mma, BK=32, 3-stage cp.async pipeline (unchanged)
// ---------------------------------------------------------------------------
#define QA_STG (128*40)
#define QB_STG (32*136)
#define QKV_SMEM_BYTES ((3*QA_STG + 3*QB_STG)*2)

__global__ __launch_bounds__(256, 2)
void qkv_gemm(void) {
    extern __shared__ __align__(16) __half qsm[];
    __half* As = qsm;
    __half* Bs = qsm + 3*QA_STG;

    const int tid  = threadIdx.x;
    const int bm   = blockIdx.y * 128, bn = blockIdx.x * 128;
    const int wid  = tid >> 5, lane = tid & 31;
    const int wm   = (wid & 1) * 64, wn = (wid >> 1) * 32;
    const int lr   = lane >> 2, lc = lane & 3;

    const int ar = tid >> 2, ach = tid & 3;
    const int br = tid >> 4, bch = tid & 15;
    const __half* asrc0 = g_xh + (size_t)(bm + ar) * DIMK + ach*8;
    const __half* asrc1 = asrc0 + (size_t)64 * DIMK;
    const __half* bsrc0 = g_wh + (size_t)br * NCOLS + bn + bch*8;
    const __half* bsrc1 = bsrc0 + (size_t)16 * NCOLS;
    const unsigned a_off = sptr(&As[ar*40 + ach*8]);
    const unsigned b_off = sptr(&Bs[br*136 + bch*8]);

    #pragma unroll
    for (int s = 0; s < 2; ++s) {
        int ko = s * 32;
        CP16(a_off + s*QA_STG*2, asrc0 + ko);
        CP16(a_off + s*QA_STG*2 + 64*40*2, asrc1 + ko);
        CP16(b_off + s*QB_STG*2, bsrc0 + (size_t)ko * NCOLS);
        CP16(b_off + s*QB_STG*2 + 16*136*2, bsrc1 + (size_t)ko * NCOLS);
        CP_COMMIT();
    }

    float cacc[4][4][4];
    #pragma unroll
    for (int i = 0; i < 4; i++)
        #pragma unroll
        for (int j = 0; j < 4; j++) { cacc[i][j][0]=0.f; cacc[i][j][1]=0.f; cacc[i][j][2]=0.f; cacc[i][j][3]=0.f; }

    const int l15 = lane & 15;
    const int lhi8 = (lane & 16) >> 1;
    int cur = 0;
    for (int kt = 0; kt < DIMK/32; ++kt) {
        CP_WAIT1();
        __syncthreads();
        if (kt + 2 < DIMK/32) {
            int ko = (kt + 2) * 32;
            int nxs = (cur + 2) % 3;
            CP16(a_off + nxs*QA_STG*2, asrc0 + ko);
            CP16(a_off + nxs*QA_STG*2 + 64*40*2, asrc1 + ko);
            CP16(b_off + nxs*QB_STG*2, bsrc0 + (size_t)ko * NCOLS);
            CP16(b_off + nxs*QB_STG*2 + 16*136*2, bsrc1 + (size_t)ko * NCOLS);
            CP_COMMIT();
        }

        const __half* Ah = As + cur*QA_STG;
        const __half* Bh = Bs + cur*QB_STG;
        #pragma unroll
        for (int ks = 0; ks < 2; ++ks) {
            unsigned af[4][4];
            #pragma unroll
            for (int mt = 0; mt < 4; ++mt)
                ldsm_x4(af[mt], sptr(&Ah[(wm + mt*16 + l15)*40 + ks*16 + lhi8]));
            #pragma unroll
            for (int ntp = 0; ntp < 2; ++ntp) {
                unsigned bf[4];
                ldsm_x4_t(bf, sptr(&Bh[(ks*16 + l15)*136 + wn + ntp*16 + lhi8]));
                #pragma unroll
                for (int mt = 0; mt < 4; ++mt) {
                    mmah(cacc[mt][2*ntp],   af[mt], bf);
                    mmah(cacc[mt][2*ntp+1], af[mt], bf + 2);
                }
            }
        }
        cur = (cur + 1) % 3;
    }

    const int part = (bn + wn) >> 10;
    __half* dst = (part == 0) ? g_qh : (part == 1) ? g_kh : g_vh;
    #pragma unroll
    for (int mt = 0; mt < 4; ++mt) {
        int r0 = bm + wm + mt*16 + lr;
        #pragma unroll
        for (int nt = 0; nt < 4; ++nt) {
            int cg = bn + wn + nt*8 + 2*lc;
            int hh = (cg >> 6) & (HEADS - 1);
            int dd = cg & 63;
            int bi = r0 >> 11, nn = r0 & 2047;
            size_t off = (((size_t)(bi*HEADS + hh) * NQ + nn) * DH) + dd;
            int r1 = r0 + 8;
            int bi1 = r1 >> 11, nn1 = r1 & 2047;
            size_t off2 = (((size_t)(bi1*HEADS + hh) * NQ + nn1) * DH) + dd;
            *(unsigned*)&dst[off]  = packh2(cacc[mt][nt][0], cacc[mt][nt][1]);
            *(unsigned*)&dst[off2] = packh2(cacc[mt][nt][2], cacc[mt][nt][3]);
        }
    }
}

// ---------------------------------------------------------------------------
// Kernel 2: fp16 flash attention with within-tile S/PV chunk skewing.
// S accumulated per 16-col chunk (ntp-outer); skew keeps one S chunk in
// flight behind each exp. Static indexing, no extra smem.
// smem: KH[2][64*72] | VH[2][64*88] (col64 = ones) | Zs[64]
// ---------------------------------------------------------------------------
#define KTK (64*72)
#define KTV (64*88)
#define ATT_SMEM_BYTES ((2*KTK + 2*KTV)*2 + 64*4)
#define SCL2 0.1803368801111204f

__device__ __forceinline__ void s_chunk(float* s0, float* s1, const __half* Kc,
                                        const unsigned qa[4][4], int ntp,
                                        int l7, int lhi8, int lane8) {
    #pragma unroll
    for (int ksd = 0; ksd < 4; ++ksd) {
        unsigned kb[4];
        ldsm_x4(kb, sptr(&Kc[(ntp*16 + l7 + lhi8)*72 + ksd*16 + lane8]));
        mmah(s0, qa[ksd], kb);
        mmah(s1, qa[ksd], kb + 2);
    }
}
__device__ __forceinline__ void exp_chunk(unsigned* a, const float* s0, const float* s1) {
    a[0] = ex2h2(s0[0], s0[1]);
    a[1] = ex2h2(s0[2], s0[3]);
    a[2] = ex2h2(s1[0], s1[1]);
    a[3] = ex2h2(s1[2], s1[3]);
}
__device__ __forceinline__ void pv_chunk(float oacc[8][4], float* osum, const __half* Vc,
                                         const unsigned* a, int kspv, int l15, int lhi8) {
    #pragma unroll
    for (int vtp = 0; vtp < 4; ++vtp) {
        unsigned vb[4];
        ldsm_x4_t(vb, sptr(&Vc[(kspv*16 + l15)*88 + vtp*16 + lhi8]));
        mmah(oacc[2*vtp],   a, vb);
        mmah(oacc[2*vtp+1], a, vb + 2);
    }
    unsigned vs[2];
    ldsm_x2_t(vs, sptr(&Vc[(kspv*16 + l15)*88 + 64]));
    mmah(osum, a, vs);
}
#define SZERO(s) { s[0]=0.f; s[1]=0.f; s[2]=0.f; s[3]=0.f; }

__global__ __launch_bounds__(256, 2)
void attn_k(const float* __restrict__ M_in, const float* __restrict__ Z_in,
            const float* __restrict__ beta_gate, float* __restrict__ outA) {
    extern __shared__ __align__(16) __half smh[];
    __half* KH = smh;
    __half* VH = smh + 2*KTK;
    float*  Zs = (float*)(smh + 2*KTK + 2*KTV);

    const int tid = threadIdx.x, wid = tid >> 5, lane = tid & 31;
    const int lr = lane >> 2, lc = lane & 3;
    const int l15 = lane & 15;
    const int l7  = lane & 7;
    const int lane8 = lane & 8;
    const int lhi8 = (lane & 16) >> 1;
    const int b = blockIdx.z, h = blockIdx.y, bh = b*HEADS + h;
    const int qb = blockIdx.x * 128;
    const int rowA = wid*16 + lr;

    const __half* qg = g_qh + ((size_t)bh*NQ + qb)*DH;
    const __half* kg = g_kh + (size_t)bh*NQ*DH;
    const __half* vg = g_vh + (size_t)bh*NQ*DH;

    const int cr = tid >> 3, cch = tid & 7;
    const unsigned k_off = sptr(&KH[cr*72 + cch*8]);
    const unsigned v_off = sptr(&VH[cr*88 + cch*8]);
    const __half* ksrc = kg + (size_t)cr*DH + cch*8;
    const __half* vsrc = vg + (size_t)cr*DH + cch*8;
    #define KROW32 (32*72*2)
    #define VROW32 (32*88*2)

    for (int i = tid; i < 128; i += 256) {
        int buf = i >> 6, r = i & 63;
        __half* vrow = VH + buf*KTV + r*88 + 64;
        vrow[0] = __float2half(1.f);
        #pragma unroll
        for (int c = 1; c < 8; ++c) vrow[c] = __float2half(0.f);
    }

    // Q fragments pre-scaled by SCL2
    unsigned qa[4][4];
    #pragma unroll
    for (int ks = 0; ks < 4; ++ks) {
        #pragma unroll
        for (int p = 0; p < 4; ++p) {
            const __half* src = qg + (size_t)(rowA + (p & 1)*8)*DH + ks*16 + 2*lc + (p >> 1)*8;
            float2 f = __half22float2(*(const __half2*)src);
            qa[ks][p] = packh2(f.x*SCL2, f.y*SCL2);
        }
    }

    CP16(k_off, ksrc); CP16(k_off + KROW32, ksrc + 32*DH);
    CP16(v_off, vsrc); CP16(v_off + VROW32, vsrc + 32*DH);
    CP_COMMIT();

    float oacc[8][4];
    #pragma unroll
    for (int i = 0; i < 8; i++) { oacc[i][0]=0.f; oacc[i][1]=0.f; oacc[i][2]=0.f; oacc[i][3]=0.f; }
    float osum[4] = {0.f, 0.f, 0.f, 0.f};

    int cur = 0;
    for (int jt = 0; jt < NQ; jt += 64) {
        CP_WAIT0();
        __syncthreads();
        if (jt + 64 < NQ) {
            int nx = cur ^ 1;
            const __half* kn = ksrc + (size_t)(jt + 64)*DH;
            const __half* vn = vsrc + (size_t)(jt + 64)*DH;
            CP16(k_off + nx*KTK*2, kn); CP16(k_off + nx*KTK*2 + KROW32, kn + 32*DH);
            CP16(v_off + nx*KTV*2, vn); CP16(v_off + nx*KTV*2 + VROW32, vn + 32*DH);
            CP_COMMIT();
        }
        const __half* Kc = KH + cur*KTK;
        const __half* Vc = VH + cur*KTV;

        // skewed S/exp/PV pipeline over 4 chunks of 16 KV columns
        float s0[4], s1[4], s2[4], s3[4], s4[4], s5[4], s6[4], s7[4];
        unsigned a0[4], a1[4], a2[4], a3[4];
        SZERO(s0); SZERO(s1);
        s_chunk(s0, s1, Kc, qa, 0, l7, lhi8, lane8);
        SZERO(s2); SZERO(s3);
        s_chunk(s2, s3, Kc, qa, 1, l7, lhi8, lane8);
        exp_chunk(a0, s0, s1);
        pv_chunk(oacc, osum, Vc, a0, 0, l15, lhi8);
        SZERO(s4); SZERO(s5);
        s_chunk(s4, s5, Kc, qa, 2, l7, lhi8, lane8);
        exp_chunk(a1, s2, s3);
        pv_chunk(oacc, osum, Vc, a1, 1, l15, lhi8);
        SZERO(s6); SZERO(s7);
        s_chunk(s6, s7, Kc, qa, 3, l7, lhi8, lane8);
        exp_chunk(a2, s4, s5);
        pv_chunk(oacc, osum, Vc, a2, 2, l15, lhi8);
        exp_chunk(a3, s6, s7);
        pv_chunk(oacc, osum, Vc, a3, 3, l15, lhi8);

        cur ^= 1;
    }

    float l1 = __shfl_sync(0xffffffffu, osum[0], lane & 28);
    float l2 = __shfl_sync(0xffffffffu, osum[2], lane & 28);

    // epilogue: A_mem = sigma(Q) @ M via fp16 mma (raw q reloaded)
    __syncthreads();
    const float* Mg = M_in + (size_t)bh*DH*DH;
    __half* Mh = KH;
    for (int i = tid; i < DH*DH; i += 256) {
        int d = i >> 6, v = i & 63;
        Mh[d*72 + v] = __float2half_rn(Mg[i]);
    }
    if (tid < DH) Zs[tid] = Z_in[bh*DH + tid];
    __syncthreads();

    float macc[8][4];
    #pragma unroll
    for (int i = 0; i < 8; i++) { macc[i][0]=0.f; macc[i][1]=0.f; macc[i][2]=0.f; macc[i][3]=0.f; }
    float den1 = 0.f, den2 = 0.f;

    #pragma unroll
    for (int ks = 0; ks < 4; ++ks) {
        unsigned a[4];
        int c0 = ks*16 + 2*lc;
        float2 f0 = __half22float2(*(const __half2*)&qg[(size_t)rowA*DH + c0]);
        float2 f1 = __half22float2(*(const __half2*)&qg[(size_t)(rowA+8)*DH + c0]);
        float2 f2 = __half22float2(*(const __half2*)&qg[(size_t)rowA*DH + c0 + 8]);
        float2 f3 = __half22float2(*(const __half2*)&qg[(size_t)(rowA+8)*DH + c0 + 8]);
        float s00 = sigma_f(f0.x), s01 = sigma_f(f0.y);
        float s10 = sigma_f(f1.x), s11 = sigma_f(f1.y);
        float s20 = sigma_f(f2.x), s21 = sigma_f(f2.y);
        float s30 = sigma_f(f3.x), s31 = sigma_f(f3.y);
        a[0] = packh2(s00, s01); a[1] = packh2(s10, s11);
        a[2] = packh2(s20, s21); a[3] = packh2(s30, s31);
        den1 += s00*Zs[c0] + s01*Zs[c0+1] + s20*Zs[c0+8] + s21*Zs[c0+9];
        den2 += s10*Zs[c0] + s11*Zs[c0+1] + s30*Zs[c0+8] + s31*Zs[c0+9];
        #pragma unroll
        for (int ntp = 0; ntp < 4; ++ntp) {
            unsigned mb[4];
            ldsm_x4_t(mb, sptr(&Mh[(ks*16 + l15)*72 + ntp*16 + lhi8]));
            mmah(macc[2*ntp],   a, mb);
            mmah(macc[2*ntp+1], a, mb + 2);
        }
    }
    den1 += __shfl_xor_sync(0xffffffffu, den1, 1);
    den1 += __shfl_xor_sync(0xffffffffu, den1, 2);
    den2 += __shfl_xor_sync(0xffffffffu, den2, 1);
    den2 += __shfl_xor_sync(0xffffffffu, den2, 2);

    float g = 1.f / (1.f + __expf(-beta_gate[h]));
    float iv1 = 1.f/l1, iv2 = 1.f/l2, id1 = 1.f/den1, id2 = 1.f/den2;

    int n1 = qb + rowA;
    float* o1 = outA + ((size_t)(b*NQ + n1))*INNER + h*DH;
    float* o2 = o1 + (size_t)8*INNER;
    #pragma unroll
    for (int nt = 0; nt < 8; ++nt) {
        int d = nt*8 + 2*lc;
        *(float2*)&o1[d] = make_float2(
            g*macc[nt][0]*id1 + (1.f-g)*oacc[nt][0]*iv1,
            g*macc[nt][1]*id1 + (1.f-g)*oacc[nt][1]*iv1);
        *(float2*)&o2[d] = make_float2(
            g*macc[nt][2]*id2 + (1.f-g)*oacc[nt][2]*iv2,
            g*macc[nt][3]*id2 + (1.f-g)*oacc[nt][3]*iv2);
    }
}

// ---------------------------------------------------------------------------
// Kernel 3: state partials via fp16 mma + fused last-CTA reduction, SPLIT=8
// ---------------------------------------------------------------------------
#define ST_SMEM_BYTES ((3*64*72)*2 + 128*4)

__global__ __launch_bounds__(256)
void state_part(const float* __restrict__ M_in, const float* __restrict__ Z_in,
                const float* __restrict__ beta_lin, float* __restrict__ out) {
    extern __shared__ __align__(16) __half sst[];
    __half* Sksh = sst;
    __half* Vsh  = sst + 64*72;
    __half* Mth  = sst + 2*64*72;
    float*  Zs   = (float*)(sst + 3*64*72);
    float*  invden = Zs + 64;
    __shared__ unsigned slast;

    const int tid = threadIdx.x, wid = tid >> 5, lane = tid & 31;
    const int lr = lane >> 2, lc = lane & 3;
    const int l15 = lane & 15, l7 = lane & 7;
    const int lhi8 = (lane & 16) >> 1;
    const int bh = blockIdx.x >> 3;
    const int chunk = blockIdx.x & 7;
    const int nrows = NQ / SPLIT;
    const int rt = wid & 3, ct = wid >> 2;

    const float* Mg = M_in + (size_t)bh*DH*DH;
    for (int i = tid; i < DH*DH; i += 256) {
        int d = i >> 6, v = i & 63;
        Mth[v*72 + d] = __float2half_rn(Mg[i]);
    }
    if (tid < DH) Zs[tid] = Z_in[bh*DH + tid];

    const __half* kg = g_kh + ((size_t)bh*NQ + (size_t)chunk*nrows)*DH;
    const __half* vg = g_vh + ((size_t)bh*NQ + (size_t)chunk*nrows)*DH;

    float macc[4][4];
    #pragma unroll
    for (int i = 0; i < 4; i++) { macc[i][0]=0.f; macc[i][1]=0.f; macc[i][2]=0.f; macc[i][3]=0.f; }
    float zpart = 0.f;
    const int dz = wid*8 + lr;

    for (int n0 = 0; n0 < nrows; n0 += 64) {
        __syncthreads();
        #pragma unroll
        for (int t = 0; t < 2; ++t) {
            int c = tid + 256*t;
            int r = c >> 3, s8 = (c & 7) << 3;
            const __half2* kp = (const __half2*)&kg[(size_t)(n0+r)*DH + s8];
            __half2 h2[4];
            #pragma unroll
            for (int u = 0; u < 4; ++u) {
                float2 f = __half22float2(kp[u]);
                h2[u] = __floats2half2_rn(sigma_f(f.x), sigma_f(f.y));
            }
            *(uint4*)&Sksh[r*72 + s8] = *(uint4*)h2;
            *(uint4*)&Vsh[r*72 + s8] = *(const uint4*)&vg[(size_t)(n0+r)*DH + s8];
        }
        __syncthreads();

        {
            int rn = wid*8 + lr;
            float acc = 0.f;
            const __half2* sp = (const __half2*)&Sksh[rn*72 + lc*16];
            #pragma unroll
            for (int j = 0; j < 8; ++j) {
                float2 f = __half22float2(sp[j]);
                acc += f.x*Zs[lc*16 + 2*j] + f.y*Zs[lc*16 + 2*j + 1];
            }
            acc += __shfl_xor_sync(0xffffffffu, acc, 1);
            acc += __shfl_xor_sync(0xffffffffu, acc, 2);
            if (lc == 0) invden[rn] = 1.f / acc;
            #pragma unroll
            for (int j = 0; j < 16; ++j)
                zpart += __half2float(Sksh[(lc*16 + j)*72 + dz]);
        }
        __syncthreads();

        float pacc[4][4];
        #pragma unroll
        for (int i = 0; i < 4; i++) { pacc[i][0]=0.f; pacc[i][1]=0.f; pacc[i][2]=0.f; pacc[i][3]=0.f; }
        #pragma unroll
        for (int ks = 0; ks < 4; ++ks) {
            unsigned af[4];
            ldsm_x4(af, sptr(&Sksh[(rt*16 + l15)*72 + ks*16 + lhi8]));
            #pragma unroll
            for (int ntp = 0; ntp < 2; ++ntp) {
                unsigned bf[4];
                ldsm_x4(bf, sptr(&Mth[(ct*32 + ntp*16 + l7 + lhi8)*72 + ks*16 + (lane & 8)]));
                mmah(pacc[2*ntp],   af, bf);
                mmah(pacc[2*ntp+1], af, bf + 2);
            }
        }

        {
            int r0 = rt*16 + lr, r1 = r0 + 8;
            float iv0 = invden[r0], iv1 = invden[r1];
            #pragma unroll
            for (int nt = 0; nt < 4; ++nt) {
                int c0 = ct*32 + nt*8 + 2*lc;
                float2 fv0 = __half22float2(*(__half2*)&Vsh[r0*72 + c0]);
                *(__half2*)&Vsh[r0*72 + c0] =
                    __floats2half2_rn(fv0.x - pacc[nt][0]*iv0, fv0.y - pacc[nt][1]*iv0);
                float2 fv1 = __half22float2(*(__half2*)&Vsh[r1*72 + c0]);
                *(__half2*)&Vsh[r1*72 + c0] =
                    __floats2half2_rn(fv1.x - pacc[nt][2]*iv1, fv1.y - pacc[nt][3]*iv1);
            }
        }
        __syncthreads();

        #pragma unroll
        for (int ks = 0; ks < 4; ++ks) {
            unsigned a[4];
            ldsm_x4_t(a, sptr(&Sksh[(ks*16 + l7 + lhi8)*72 + rt*16 + (lane & 8)]));
            #pragma unroll
            for (int ntp = 0; ntp < 2; ++ntp) {
                unsigned bf[4];
                ldsm_x4_t(bf, sptr(&Vsh[(ks*16 + l15)*72 + ct*32 + ntp*16 + lhi8]));
                mmah(macc[2*ntp],   a, bf);
                mmah(macc[2*ntp+1], a, bf + 2);
            }
        }
    }

    float* mp = g_mpart + (size_t)blockIdx.x * DH*DH;
    int d0 = rt*16 + lr, d1 = d0 + 8;
    #pragma unroll
    for (int nt = 0; nt < 4; ++nt) {
        int c0 = ct*32 + nt*8 + 2*lc;
        *(float2*)&mp[d0*DH + c0] = make_float2(macc[nt][0], macc[nt][1]);
        *(float2*)&mp[d1*DH + c0] = make_float2(macc[nt][2], macc[nt][3]);
    }
    zpart += __shfl_xor_sync(0xffffffffu, zpart, 1);
    zpart += __shfl_xor_sync(0xffffffffu, zpart, 2);
    if (lc == 0) g_zpart[blockIdx.x*DH + dz] = zpart;

    __threadfence();
    if (tid == 0) slast = atomicInc(&g_cnt[bh], SPLIT - 1);
    __syncthreads();
    if (slast == SPLIT - 1) {
        float beta = 1.f / (1.f + __expf(-beta_lin[0]));
        beta = fminf(fmaxf(beta, 0.9f), 0.999f);
        float* mo = out + A_ELEMS + (size_t)bh*DH*DH;
        for (int e = tid; e < DH*DH; e += 256) {
            float s = beta*Mg[e];
            #pragma unroll
            for (int c = 0; c < SPLIT; ++c)
                s += g_mpart[(size_t)(bh*SPLIT + c)*DH*DH + e];
            mo[e] = s;
        }
        if (tid < DH) {
            float z = 0.f;
            #pragma unroll
            for (int c = 0; c < SPLIT; ++c)
                z += g_zpart[(bh*SPLIT + c)*DH + tid];
            out[A_ELEMS + M_ELEMS + bh*DH + tid] = beta*Z_in[bh*DH + tid] + z;
        }
    }
}

// ---------------------------------------------------------------------------
extern "C" void kernel_launch(void* const* d_in, const int* in_sizes, int n_in,
                              void* d_out, int out_size) {
    const float* x         = (const float*)d_in[0];
    const float* M         = (const float*)d_in[1];
    const float* Z         = (const float*)d_in[2];
    const float* W         = (const float*)d_in[3];
    const float* beta_lin  = (const float*)d_in[4];
    const float* beta_gate = (const float*)d_in[5];
    float* out = (float*)d_out;

    cudaFuncSetAttribute(qkv_gemm, cudaFuncAttributeMaxDynamicSharedMemorySize, QKV_SMEM_BYTES);
    cudaFuncSetAttribute(attn_k, cudaFuncAttributeMaxDynamicSharedMemorySize, ATT_SMEM_BYTES);
    cudaFuncSetAttribute(state_part, cudaFuncAttributeMaxDynamicSharedMemorySize, ST_SMEM_BYTES);

    const int npc = (BB*NQ*DIMK + DIMK*NCOLS)/4;
    preconv<<<(npc + 1023)/1024, 256>>>(x, W);
    qkv_gemm<<<dim3(NCOLS/128, (BB*NQ)/128), 256, QKV_SMEM_BYTES>>>();
    attn_k<<<dim3(NQ/128, HEADS, BB), 256, ATT_SMEM_BYTES>>>(M, Z, beta_gate, out);
    state_part<<<BB*HEADS*SPLIT, 256, ST_SMEM_BYTES>>>(M, Z, beta_lin, out);
}